// round 6
// baseline (speedup 1.0000x reference)
#include <cuda_runtime.h>
#include <math.h>
#include <stdint.h>

// Model dims (fixed by the problem)
#define L_  8
#define H_  16
#define D_  1024
#define DH_ 64
#define FF_ 4096
#define V_  32000
#define S_  1024
#define B_  2
#define ROWS (B_*S_)   // 2048
#define QKVW (3*D_)    // 3072

// ---------------- scratch (static device globals; no allocation allowed) ----
__device__ float g_Wqkv[L_*D_*QKVW];   // packed [L][D][3072] (q|k|v, head-concat)
__device__ float g_bqkv[L_*QKVW];
__device__ float g_h  [ROWS*D_];
__device__ float g_qkv[ROWS*QKVW];
__device__ float g_att[ROWS*D_];
__device__ float g_tmp[ROWS*D_];
__device__ float g_ff [ROWS*FF_];

// ---------------- pack wq/wk/wv -> [L][D][3072] ------------------------------
__global__ void pack_qkv_kernel(const float* __restrict__ wq, const float* __restrict__ wk,
                                const float* __restrict__ wv, float* __restrict__ W) {
    int i = blockIdx.x * blockDim.x + threadIdx.x;
    if (i >= L_*D_*QKVW) return;
    int l = i / (D_*QKVW);
    int r = i - l*(D_*QKVW);
    int d = r / QKVW;
    int n = r - d*QKVW;
    int sect = n >> 10;         // 0:q 1:k 2:v
    int hn   = n & 1023;
    int h    = hn >> 6;
    int e    = hn & 63;
    const float* src = (sect == 0) ? wq : (sect == 1 ? wk : wv);
    W[i] = src[(((size_t)l*H_ + h)*D_ + d)*DH_ + e];
}

__global__ void pack_bias_kernel(const float* __restrict__ bq, const float* __restrict__ bk,
                                 const float* __restrict__ bv, float* __restrict__ bias) {
    int i = blockIdx.x * blockDim.x + threadIdx.x;
    if (i >= L_*QKVW) return;
    int l = i / QKVW;
    int n = i - l*QKVW;
    int sect = n >> 10;
    int hn   = n & 1023;
    const float* src = (sect == 0) ? bq : (sect == 1 ? bk : bv);
    bias[i] = src[(size_t)l*D_ + hn];
}

// ---------------- embedding: h = tok_emb[x] + pos_emb ----------------------
__global__ void embed_kernel(const int* __restrict__ x, const float* __restrict__ tok,
                             const float* __restrict__ pos, float* __restrict__ out) {
    int i = blockIdx.x * blockDim.x + threadIdx.x;
    if (i >= ROWS*D_) return;
    int bs = i / D_;
    int d  = i - bs*D_;
    int s  = bs & (S_-1);
    int t  = x[bs];
    out[i] = tok[(size_t)t*D_ + d] + pos[(size_t)s*D_ + d];
}

// ---------------- tf32 tensor-core GEMM:  C = A[MxK] @ B[KxN] + bias --------
// 128x128 CTA tile, BK=16, 128 threads (4 warps, each 64x64),
// mma.sync.m16n8k8 tf32, 3-stage cp.async pipeline.
#define BM 128
#define BN 128
#define BK 16
#define STAGES 3
// SMEM floats: As[3][128][20] + Bs[3][16][136]
#define AS_STRIDE 20
#define BS_STRIDE 136
#define AS_STAGE (BM*AS_STRIDE)          // 2560 floats
#define BS_STAGE (BK*BS_STRIDE)          // 2176 floats
#define GEMM_SMEM ((STAGES*(AS_STAGE + BS_STAGE))*4)   // 56832 bytes

#define CP16(dst_u32, src_ptr) \
    asm volatile("cp.async.cg.shared.global [%0], [%1], 16;\n" :: "r"(dst_u32), "l"(src_ptr))

__device__ __forceinline__ void mma_tf32(float c[4], const uint32_t a[4], const uint32_t b[2]) {
    asm volatile(
        "mma.sync.aligned.m16n8k8.row.col.f32.tf32.tf32.f32 "
        "{%0,%1,%2,%3}, {%4,%5,%6,%7}, {%8,%9}, {%0,%1,%2,%3};\n"
        : "+f"(c[0]), "+f"(c[1]), "+f"(c[2]), "+f"(c[3])
        : "r"(a[0]), "r"(a[1]), "r"(a[2]), "r"(a[3]), "r"(b[0]), "r"(b[1]));
}

template<bool RELU>
__global__ __launch_bounds__(128)
void gemm_tc_kernel(const float* __restrict__ A, const float* __restrict__ B,
                    const float* __restrict__ bias, float* __restrict__ C,
                    int M, int N, int K) {
    extern __shared__ float sm[];
    float* AsBase = sm;                           // [STAGES][BM][20]
    float* BsBase = sm + STAGES*AS_STAGE;         // [STAGES][BK][136]

    const int tid   = threadIdx.x;
    const int warp  = tid >> 5;
    const int lane  = tid & 31;
    const int warpM = warp >> 1;        // 0..1 -> 64-row slab
    const int warpN = warp & 1;         // 0..1 -> 64-col slab
    const int gid   = lane >> 2;        // 0..7
    const int tig   = lane & 3;         // 0..3

    const int bm = blockIdx.y * BM;
    const int bn = blockIdx.x * BN;

    float acc[4][8][4];
#pragma unroll
    for (int mt = 0; mt < 4; mt++)
#pragma unroll
        for (int nt = 0; nt < 8; nt++)
#pragma unroll
            for (int i = 0; i < 4; i++) acc[mt][nt][i] = 0.f;

    const int KT = K / BK;

    // per-stage copy: A tile 128x16 (512 f4), B tile 16x128 (512 f4); 4 each/thread
    auto copy_tile = [&](int k0, int st) {
        float* As = AsBase + st*AS_STAGE;
        float* Bs = BsBase + st*BS_STAGE;
#pragma unroll
        for (int i = 0; i < 4; i++) {
            int idx = tid + i*128;
            int row = idx >> 2;
            int kc  = (idx & 3) << 2;
            const float* src = A + (size_t)(bm + row)*K + k0 + kc;
            uint32_t dst = (uint32_t)__cvta_generic_to_shared(As + row*AS_STRIDE + kc);
            CP16(dst, src);
        }
#pragma unroll
        for (int i = 0; i < 4; i++) {
            int idx = tid + i*128;
            int row = idx >> 5;
            int nc  = (idx & 31) << 2;
            const float* src = B + (size_t)(k0 + row)*N + bn + nc;
            uint32_t dst = (uint32_t)__cvta_generic_to_shared(Bs + row*BS_STRIDE + nc);
            CP16(dst, src);
        }
        asm volatile("cp.async.commit_group;\n");
    };

    copy_tile(0, 0);
    if (KT > 1) copy_tile(BK, 1);

    int st = 0;
    for (int s = 0; s < KT; s++) {
        if (s + 1 < KT) asm volatile("cp.async.wait_group 1;\n");
        else            asm volatile("cp.async.wait_group 0;\n");
        __syncthreads();
        if (s + 2 < KT) {
            int nst = st + 2; if (nst >= STAGES) nst -= STAGES;
            copy_tile((s + 2) * BK, nst);
        }

        const float* As = AsBase + st*AS_STAGE;
        const float* Bs = BsBase + st*BS_STAGE;
#pragma unroll
        for (int kk = 0; kk < 2; kk++) {
            const int kb = kk * 8;
            uint32_t af[4][4];
#pragma unroll
            for (int mt = 0; mt < 4; mt++) {
                int r0 = warpM*64 + mt*16 + gid;
                af[mt][0] = __float_as_uint(As[(r0    )*AS_STRIDE + kb + tig    ]);
                af[mt][1] = __float_as_uint(As[(r0 + 8)*AS_STRIDE + kb + tig    ]);
                af[mt][2] = __float_as_uint(As[(r0    )*AS_STRIDE + kb + tig + 4]);
                af[mt][3] = __float_as_uint(As[(r0 + 8)*AS_STRIDE + kb + tig + 4]);
            }
#pragma unroll
            for (int nt = 0; nt < 8; nt++) {
                int c0 = warpN*64 + nt*8 + gid;
                uint32_t bf[2];
                bf[0] = __float_as_uint(Bs[(kb + tig    )*BS_STRIDE + c0]);
                bf[1] = __float_as_uint(Bs[(kb + tig + 4)*BS_STRIDE + c0]);
#pragma unroll
                for (int mt = 0; mt < 4; mt++) mma_tf32(acc[mt][nt], af[mt], bf);
            }
        }
        st++; if (st >= STAGES) st = 0;
    }

    // epilogue: bias (+relu), float2 stores
#pragma unroll
    for (int mt = 0; mt < 4; mt++) {
#pragma unroll
        for (int nt = 0; nt < 8; nt++) {
            int row = bm + warpM*64 + mt*16 + gid;
            int col = bn + warpN*64 + nt*8 + tig*2;
            float b0 = bias[col], b1 = bias[col + 1];
            float v0 = acc[mt][nt][0] + b0;
            float v1 = acc[mt][nt][1] + b1;
            float v2 = acc[mt][nt][2] + b0;
            float v3 = acc[mt][nt][3] + b1;
            if (RELU) {
                v0 = fmaxf(v0, 0.f); v1 = fmaxf(v1, 0.f);
                v2 = fmaxf(v2, 0.f); v3 = fmaxf(v3, 0.f);
            }
            *(float2*)(C + (size_t)row*N + col)       = make_float2(v0, v1);
            *(float2*)(C + (size_t)(row + 8)*N + col) = make_float2(v2, v3);
        }
    }
}

// ---------------- causal flash attention (fp32) on packed qkv ---------------
// grid: (S/128, B*H). 128 threads; 1 thread = 1 query row. K/V tiled 32 keys.
__global__ __launch_bounds__(128, 2)
void attn_kernel(const float* __restrict__ qkv, float* __restrict__ o) {
    const int tid = threadIdx.x;                  // 0..127
    const int s   = blockIdx.x * 128 + tid;       // query position
    const int bh  = blockIdx.y;
    const int b   = bh >> 4;                      // /H_
    const int h   = bh & 15;
    const float scale = 0.125f;                   // 1/sqrt(64)

    __shared__ float ks[32][64];
    __shared__ float vs[32][64];

    const float* qrow = qkv + (size_t)(b*S_ + s)*QKVW + h*DH_;
    float qr[64], acc[64];
#pragma unroll
    for (int d = 0; d < 64; d++) { qr[d] = qrow[d]; acc[d] = 0.f; }
    float m = -1e30f, lsum = 0.f;

    const int kt_max = (blockIdx.x*128 + 127) >> 5;   // inclusive
    for (int kt = 0; kt <= kt_max; kt++) {
        const float* kbase = qkv + (size_t)(b*S_ + kt*32)*QKVW + D_   + h*DH_;
        const float* vbase = qkv + (size_t)(b*S_ + kt*32)*QKVW + 2*D_ + h*DH_;
#pragma unroll
        for (int i = 0; i < 4; i++) {
            int idx = tid + i*128;         // 0..511 float4 slots (32x16)
            int r = idx >> 4;
            int c = (idx & 15) << 2;
            *(float4*)&ks[r][c] = *(const float4*)(kbase + (size_t)r*QKVW + c);
            *(float4*)&vs[r][c] = *(const float4*)(vbase + (size_t)r*QKVW + c);
        }
        __syncthreads();

        float sc[32];
        float tmax = -1e30f;
#pragma unroll
        for (int t = 0; t < 32; t++) {
            float dot = 0.f;
#pragma unroll
            for (int d = 0; d < 64; d++) dot += qr[d]*ks[t][d];
            int kk = kt*32 + t;
            sc[t] = (kk <= s) ? dot*scale : -1e30f;
            tmax = fmaxf(tmax, sc[t]);
        }
        float mnew = fmaxf(m, tmax);
        float corr = __expf(m - mnew);
        lsum *= corr;
#pragma unroll
        for (int d = 0; d < 64; d++) acc[d] *= corr;
#pragma unroll
        for (int t = 0; t < 32; t++) {
            float p = __expf(sc[t] - mnew);
            lsum += p;
#pragma unroll
            for (int d = 0; d < 64; d++) acc[d] += p * vs[t][d];
        }
        m = mnew;
        __syncthreads();
    }
    float inv = 1.f / lsum;
    float* orow = o + (size_t)(b*S_ + s)*D_ + h*DH_;
#pragma unroll
    for (int d = 0; d < 64; d++) orow[d] = acc[d]*inv;
}

// ---------------- residual add + LayerNorm (in-place into hres) -------------
__global__ void add_ln_kernel(const float* __restrict__ a, float* __restrict__ hres,
                              const float* __restrict__ g, const float* __restrict__ bta) {
    const int row = blockIdx.x;
    const int tid = threadIdx.x;   // 256
    __shared__ float xs[D_];
    __shared__ float rbuf[2][8];
    __shared__ float stats[2];

    float s1 = 0.f, s2 = 0.f;
    for (int i = tid; i < D_; i += 256) {
        float x = a[(size_t)row*D_+i] + hres[(size_t)row*D_+i];
        xs[i] = x; s1 += x; s2 += x*x;
    }
#pragma unroll
    for (int off = 16; off; off >>= 1) {
        s1 += __shfl_down_sync(0xffffffffu, s1, off);
        s2 += __shfl_down_sync(0xffffffffu, s2, off);
    }
    if ((tid & 31) == 0) { rbuf[0][tid>>5] = s1; rbuf[1][tid>>5] = s2; }
    __syncthreads();
    if (tid == 0) {
        float t1 = 0.f, t2 = 0.f;
        for (int w = 0; w < 8; w++) { t1 += rbuf[0][w]; t2 += rbuf[1][w]; }
        float mu  = t1 * (1.f/D_);
        float var = t2 * (1.f/D_) - mu*mu;
        stats[0] = mu; stats[1] = rsqrtf(var + 1e-5f);
    }
    __syncthreads();
    float mu = stats[0], rstd = stats[1];
    for (int i = tid; i < D_; i += 256)
        hres[(size_t)row*D_+i] = (xs[i]-mu)*rstd*g[i] + bta[i];
}

// ---------------- log_softmax over V, in-place -------------------------------
__global__ void logsoftmax_kernel(float* __restrict__ out) {
    const int row = blockIdx.x;
    const int tid = threadIdx.x;   // 256
    float* p = out + (size_t)row * V_;
    __shared__ float rbuf[8];
    __shared__ float smax, slse;

    float lmax = -1e30f;
    for (int i = tid; i < V_; i += 256) lmax = fmaxf(lmax, p[i]);
#pragma unroll
    for (int off = 16; off; off >>= 1)
        lmax = fmaxf(lmax, __shfl_down_sync(0xffffffffu, lmax, off));
    if ((tid & 31) == 0) rbuf[tid>>5] = lmax;
    __syncthreads();
    if (tid == 0) {
        float mtot = -1e30f;
        for (int w = 0; w < 8; w++) mtot = fmaxf(mtot, rbuf[w]);
        smax = mtot;
    }
    __syncthreads();
    float mx = smax;

    float lsum = 0.f;
    for (int i = tid; i < V_; i += 256) lsum += __expf(p[i] - mx);
#pragma unroll
    for (int off = 16; off; off >>= 1)
        lsum += __shfl_down_sync(0xffffffffu, lsum, off);
    if ((tid & 31) == 0) rbuf[tid>>5] = lsum;
    __syncthreads();
    if (tid == 0) {
        float stot = 0.f;
        for (int w = 0; w < 8; w++) stot += rbuf[w];
        slse = logf(stot) + mx;
    }
    __syncthreads();
    float lse = slse;
    for (int i = tid; i < V_; i += 256) p[i] = p[i] - lse;
}

// ---------------- host-side helpers ------------------------------------------
static inline void gemm(const float* A, const float* B, const float* bias, float* C,
                        int M, int N, int K, bool relu) {
    dim3 g(N/BN, M/BM);
    if (relu) gemm_tc_kernel<true ><<<g, 128, GEMM_SMEM>>>(A, B, bias, C, M, N, K);
    else      gemm_tc_kernel<false><<<g, 128, GEMM_SMEM>>>(A, B, bias, C, M, N, K);
}

extern "C" void kernel_launch(void* const* d_in, const int* in_sizes, int n_in,
                              void* d_out, int out_size) {
    const int*   x    = (const int*)  d_in[0];
    const float* tok  = (const float*)d_in[1];
    const float* pos  = (const float*)d_in[2];
    const float* wq   = (const float*)d_in[3];
    const float* bq   = (const float*)d_in[4];
    const float* wk   = (const float*)d_in[5];
    const float* bk   = (const float*)d_in[6];
    const float* wv   = (const float*)d_in[7];
    const float* bv   = (const float*)d_in[8];
    const float* wo   = (const float*)d_in[9];
    const float* bo   = (const float*)d_in[10];
    const float* ln1g = (const float*)d_in[11];
    const float* ln1b = (const float*)d_in[12];
    const float* w1   = (const float*)d_in[13];
    const float* b1   = (const float*)d_in[14];
    const float* w2   = (const float*)d_in[15];
    const float* b2   = (const float*)d_in[16];
    const float* ln2g = (const float*)d_in[17];
    const float* ln2b = (const float*)d_in[18];
    const float* wout = (const float*)d_in[19];
    const float* bout = (const float*)d_in[20];
    float* out = (float*)d_out;

    cudaFuncSetAttribute(gemm_tc_kernel<true >, cudaFuncAttributeMaxDynamicSharedMemorySize, GEMM_SMEM);
    cudaFuncSetAttribute(gemm_tc_kernel<false>, cudaFuncAttributeMaxDynamicSharedMemorySize, GEMM_SMEM);

    float *Wqkv, *bqkv, *h, *qkv, *att, *tmp, *ff;
    cudaGetSymbolAddress((void**)&Wqkv, g_Wqkv);
    cudaGetSymbolAddress((void**)&bqkv, g_bqkv);
    cudaGetSymbolAddress((void**)&h,    g_h);
    cudaGetSymbolAddress((void**)&qkv,  g_qkv);
    cudaGetSymbolAddress((void**)&att,  g_att);
    cudaGetSymbolAddress((void**)&tmp,  g_tmp);
    cudaGetSymbolAddress((void**)&ff,   g_ff);

    // pack qkv weights/biases
    {
        int n = L_*D_*QKVW;
        pack_qkv_kernel<<<(n + 255)/256, 256>>>(wq, wk, wv, Wqkv);
        int nb = L_*QKVW;
        pack_bias_kernel<<<(nb + 255)/256, 256>>>(bq, bk, bv, bqkv);
    }

    // embedding
    embed_kernel<<<(ROWS*D_ + 255)/256, 256>>>(x, tok, pos, h);

    for (int l = 0; l < L_; l++) {
        gemm(h, Wqkv + (size_t)l*D_*QKVW, bqkv + (size_t)l*QKVW, qkv, ROWS, QKVW, D_, false);

        dim3 ag(S_/128, B_*H_);
        attn_kernel<<<ag, 128>>>(qkv, att);

        gemm(att, wo + (size_t)l*D_*D_, bo + (size_t)l*D_, tmp, ROWS, D_, D_, false);
        add_ln_kernel<<<ROWS, 256>>>(tmp, h, ln1g + (size_t)l*D_, ln1b + (size_t)l*D_);

        gemm(h,  w1 + (size_t)l*D_*FF_, b1 + (size_t)l*FF_, ff,  ROWS, FF_, D_, true);
        gemm(ff, w2 + (size_t)l*FF_*D_, b2 + (size_t)l*D_,  tmp, ROWS, D_,  FF_, false);
        add_ln_kernel<<<ROWS, 256>>>(tmp, h, ln2g + (size_t)l*D_, ln2b + (size_t)l*D_);
    }

    // final vocab projection + log_softmax (in-place on d_out)
    gemm(h, wout, bout, out, ROWS, V_, D_, false);
    logsoftmax_kernel<<<ROWS, 256>>>(out);
}

// round 10
// speedup vs baseline: 1.0249x; 1.0249x over previous
#include <cuda_runtime.h>
#include <math.h>
#include <stdint.h>

// Model dims (fixed by the problem)
#define L_  8
#define H_  16
#define D_  1024
#define DH_ 64
#define FF_ 4096
#define V_  32000
#define S_  1024
#define B_  2
#define ROWS (B_*S_)   // 2048
#define QKVW (3*D_)    // 3072

// ---------------- scratch (static device globals; no allocation allowed) ----
__device__ float g_Wqkv[L_*D_*QKVW];   // packed [L][D][3072] (q|k|v, head-concat)
__device__ float g_bqkv[L_*QKVW];
__device__ float g_h  [ROWS*D_];
__device__ float g_qkv[ROWS*QKVW];
__device__ float g_att[ROWS*D_];
__device__ float g_tmp[ROWS*D_];
__device__ float g_ff [ROWS*FF_];

// ---------------- pack wq/wk/wv -> [L][D][3072] ------------------------------
__global__ void pack_qkv_kernel(const float* __restrict__ wq, const float* __restrict__ wk,
                                const float* __restrict__ wv, float* __restrict__ W) {
    int i = blockIdx.x * blockDim.x + threadIdx.x;
    if (i >= L_*D_*QKVW) return;
    int l = i / (D_*QKVW);
    int r = i - l*(D_*QKVW);
    int d = r / QKVW;
    int n = r - d*QKVW;
    int sect = n >> 10;         // 0:q 1:k 2:v
    int hn   = n & 1023;
    int h    = hn >> 6;
    int e    = hn & 63;
    const float* src = (sect == 0) ? wq : (sect == 1 ? wk : wv);
    W[i] = src[(((size_t)l*H_ + h)*D_ + d)*DH_ + e];
}

__global__ void pack_bias_kernel(const float* __restrict__ bq, const float* __restrict__ bk,
                                 const float* __restrict__ bv, float* __restrict__ bias) {
    int i = blockIdx.x * blockDim.x + threadIdx.x;
    if (i >= L_*QKVW) return;
    int l = i / QKVW;
    int n = i - l*QKVW;
    int sect = n >> 10;
    int hn   = n & 1023;
    const float* src = (sect == 0) ? bq : (sect == 1 ? bk : bv);
    bias[i] = src[(size_t)l*D_ + hn];
}

// ---------------- embedding: h = tok_emb[x] + pos_emb ----------------------
__global__ void embed_kernel(const int* __restrict__ x, const float* __restrict__ tok,
                             const float* __restrict__ pos, float* __restrict__ out) {
    int i = blockIdx.x * blockDim.x + threadIdx.x;
    if (i >= ROWS*D_) return;
    int bs = i / D_;
    int d  = i - bs*D_;
    int s  = bs & (S_-1);
    int t  = x[bs];
    out[i] = tok[(size_t)t*D_ + d] + pos[(size_t)s*D_ + d];
}

// ---------------- tf32 tensor-core GEMM:  C = A[MxK] @ B[KxN] + bias --------
// 128x128 CTA tile, BK=32, 128 threads (4 warps, each 64x64),
// mma.sync.m16n8k8 tf32, 2-stage cp.async pipeline, 3 CTAs/SM.
#define BM 128
#define BN 128
#define BK 32
// SMEM floats: As[2][128][36] + Bs[2][32][136]
#define AS_STRIDE 36
#define BS_STRIDE 136
#define AS_STAGE (BM*AS_STRIDE)          // 4608 floats
#define BS_STAGE (BK*BS_STRIDE)          // 4352 floats
#define GEMM_SMEM ((2*(AS_STAGE + BS_STAGE))*4)   // 71680 bytes

#define CP16(dst_u32, src_ptr) \
    asm volatile("cp.async.cg.shared.global [%0], [%1], 16;\n" :: "r"(dst_u32), "l"(src_ptr))

__device__ __forceinline__ void mma_tf32(float c[4], const uint32_t a[4], const uint32_t b[2]) {
    asm volatile(
        "mma.sync.aligned.m16n8k8.row.col.f32.tf32.tf32.f32 "
        "{%0,%1,%2,%3}, {%4,%5,%6,%7}, {%8,%9}, {%0,%1,%2,%3};\n"
        : "+f"(c[0]), "+f"(c[1]), "+f"(c[2]), "+f"(c[3])
        : "r"(a[0]), "r"(a[1]), "r"(a[2]), "r"(a[3]), "r"(b[0]), "r"(b[1]));
}

template<bool RELU>
__global__ __launch_bounds__(128, 3)
void gemm_tc_kernel(const float* __restrict__ A, const float* __restrict__ B,
                    const float* __restrict__ bias, float* __restrict__ C,
                    int M, int N, int K) {
    extern __shared__ float sm[];
    float* AsBase = sm;                      // [2][BM][36]
    float* BsBase = sm + 2*AS_STAGE;         // [2][BK][136]

    const int tid   = threadIdx.x;
    const int warp  = tid >> 5;
    const int lane  = tid & 31;
    const int warpM = warp >> 1;        // 0..1 -> 64-row slab
    const int warpN = warp & 1;         // 0..1 -> 64-col slab
    const int gid   = lane >> 2;        // 0..7
    const int tig   = lane & 3;         // 0..3

    const int bm = blockIdx.y * BM;
    const int bn = blockIdx.x * BN;

    float acc[4][8][4];
#pragma unroll
    for (int mt = 0; mt < 4; mt++)
#pragma unroll
        for (int nt = 0; nt < 8; nt++)
#pragma unroll
            for (int i = 0; i < 4; i++) acc[mt][nt][i] = 0.f;

    const int KT = K / BK;

    // per-stage copy: A tile 128x32 (1024 f4), B tile 32x128 (1024 f4); 8 each/thread
    auto copy_tile = [&](int k0, int st) {
        float* As = AsBase + st*AS_STAGE;
        float* Bs = BsBase + st*BS_STAGE;
#pragma unroll
        for (int i = 0; i < 8; i++) {
            int idx = tid + i*128;
            int row = idx >> 3;
            int kc  = (idx & 7) << 2;
            const float* src = A + (size_t)(bm + row)*K + k0 + kc;
            uint32_t dst = (uint32_t)__cvta_generic_to_shared(As + row*AS_STRIDE + kc);
            CP16(dst, src);
        }
#pragma unroll
        for (int i = 0; i < 8; i++) {
            int idx = tid + i*128;
            int row = idx >> 5;
            int nc  = (idx & 31) << 2;
            const float* src = B + (size_t)(k0 + row)*N + bn + nc;
            uint32_t dst = (uint32_t)__cvta_generic_to_shared(Bs + row*BS_STRIDE + nc);
            CP16(dst, src);
        }
        asm volatile("cp.async.commit_group;\n");
    };

    copy_tile(0, 0);

    for (int s = 0; s < KT; s++) {
        const int st = s & 1;
        asm volatile("cp.async.wait_group 0;\n");
        __syncthreads();
        if (s + 1 < KT) copy_tile((s + 1) * BK, st ^ 1);

        const float* As = AsBase + st*AS_STAGE;
        const float* Bs = BsBase + st*BS_STAGE;
#pragma unroll
        for (int kk = 0; kk < 4; kk++) {
            const int kb = kk * 8;
            uint32_t af[4][4];
#pragma unroll
            for (int mt = 0; mt < 4; mt++) {
                int r0 = warpM*64 + mt*16 + gid;
                af[mt][0] = __float_as_uint(As[(r0    )*AS_STRIDE + kb + tig    ]);
                af[mt][1] = __float_as_uint(As[(r0 + 8)*AS_STRIDE + kb + tig    ]);
                af[mt][2] = __float_as_uint(As[(r0    )*AS_STRIDE + kb + tig + 4]);
                af[mt][3] = __float_as_uint(As[(r0 + 8)*AS_STRIDE + kb + tig + 4]);
            }
#pragma unroll
            for (int nt = 0; nt < 8; nt++) {
                int c0 = warpN*64 + nt*8 + gid;
                uint32_t bf[2];
                bf[0] = __float_as_uint(Bs[(kb + tig    )*BS_STRIDE + c0]);
                bf[1] = __float_as_uint(Bs[(kb + tig + 4)*BS_STRIDE + c0]);
#pragma unroll
                for (int mt = 0; mt < 4; mt++) mma_tf32(acc[mt][nt], af[mt], bf);
            }
        }
        __syncthreads();
    }

    // epilogue: bias (+relu), float2 stores
#pragma unroll
    for (int mt = 0; mt < 4; mt++) {
#pragma unroll
        for (int nt = 0; nt < 8; nt++) {
            int row = bm + warpM*64 + mt*16 + gid;
            int col = bn + warpN*64 + nt*8 + tig*2;
            float b0 = bias[col], b1 = bias[col + 1];
            float v0 = acc[mt][nt][0] + b0;
            float v1 = acc[mt][nt][1] + b1;
            float v2 = acc[mt][nt][2] + b0;
            float v3 = acc[mt][nt][3] + b1;
            if (RELU) {
                v0 = fmaxf(v0, 0.f); v1 = fmaxf(v1, 0.f);
                v2 = fmaxf(v2, 0.f); v3 = fmaxf(v3, 0.f);
            }
            *(float2*)(C + (size_t)row*N + col)       = make_float2(v0, v1);
            *(float2*)(C + (size_t)(row + 8)*N + col) = make_float2(v2, v3);
        }
    }
}

// ---------------- causal flash attention (fp32) on packed qkv ---------------
// grid: (S/128, B*H). 128 threads; 1 thread = 1 query row. K/V tiled 32 keys.
__global__ __launch_bounds__(128, 2)
void attn_kernel(const float* __restrict__ qkv, float* __restrict__ o) {
    const int tid = threadIdx.x;                  // 0..127
    const int s   = blockIdx.x * 128 + tid;       // query position
    const int bh  = blockIdx.y;
    const int b   = bh >> 4;                      // /H_
    const int h   = bh & 15;
    const float scale = 0.125f;                   // 1/sqrt(64)

    __shared__ float ks[32][64];
    __shared__ float vs[32][64];

    const float* qrow = qkv + (size_t)(b*S_ + s)*QKVW + h*DH_;
    float qr[64], acc[64];
#pragma unroll
    for (int d = 0; d < 64; d++) { qr[d] = qrow[d]; acc[d] = 0.f; }
    float m = -1e30f, lsum = 0.f;

    const int kt_max = (blockIdx.x*128 + 127) >> 5;   // inclusive
    for (int kt = 0; kt <= kt_max; kt++) {
        const float* kbase = qkv + (size_t)(b*S_ + kt*32)*QKVW + D_   + h*DH_;
        const float* vbase = qkv + (size_t)(b*S_ + kt*32)*QKVW + 2*D_ + h*DH_;
#pragma unroll
        for (int i = 0; i < 4; i++) {
            int idx = tid + i*128;         // 0..511 float4 slots (32x16)
            int r = idx >> 4;
            int c = (idx & 15) << 2;
            *(float4*)&ks[r][c] = *(const float4*)(kbase + (size_t)r*QKVW + c);
            *(float4*)&vs[r][c] = *(const float4*)(vbase + (size_t)r*QKVW + c);
        }
        __syncthreads();

        float sc[32];
        float tmax = -1e30f;
#pragma unroll
        for (int t = 0; t < 32; t++) {
            float dot = 0.f;
#pragma unroll
            for (int d = 0; d < 64; d++) dot += qr[d]*ks[t][d];
            int kk = kt*32 + t;
            sc[t] = (kk <= s) ? dot*scale : -1e30f;
            tmax = fmaxf(tmax, sc[t]);
        }
        float mnew = fmaxf(m, tmax);
        float corr = __expf(m - mnew);
        lsum *= corr;
#pragma unroll
        for (int d = 0; d < 64; d++) acc[d] *= corr;
#pragma unroll
        for (int t = 0; t < 32; t++) {
            float p = __expf(sc[t] - mnew);
            lsum += p;
#pragma unroll
            for (int d = 0; d < 64; d++) acc[d] += p * vs[t][d];
        }
        m = mnew;
        __syncthreads();
    }
    float inv = 1.f / lsum;
    float* orow = o + (size_t)(b*S_ + s)*D_ + h*DH_;
#pragma unroll
    for (int d = 0; d < 64; d++) orow[d] = acc[d]*inv;
}

// ---------------- residual add + LayerNorm (in-place into hres) -------------
__global__ void add_ln_kernel(const float* __restrict__ a, float* __restrict__ hres,
                              const float* __restrict__ g, const float* __restrict__ bta) {
    const int row = blockIdx.x;
    const int tid = threadIdx.x;   // 256
    __shared__ float xs[D_];
    __shared__ float rbuf[2][8];
    __shared__ float stats[2];

    float s1 = 0.f, s2 = 0.f;
    for (int i = tid; i < D_; i += 256) {
        float x = a[(size_t)row*D_+i] + hres[(size_t)row*D_+i];
        xs[i] = x; s1 += x; s2 += x*x;
    }
#pragma unroll
    for (int off = 16; off; off >>= 1) {
        s1 += __shfl_down_sync(0xffffffffu, s1, off);
        s2 += __shfl_down_sync(0xffffffffu, s2, off);
    }
    if ((tid & 31) == 0) { rbuf[0][tid>>5] = s1; rbuf[1][tid>>5] = s2; }
    __syncthreads();
    if (tid == 0) {
        float t1 = 0.f, t2 = 0.f;
        for (int w = 0; w < 8; w++) { t1 += rbuf[0][w]; t2 += rbuf[1][w]; }
        float mu  = t1 * (1.f/D_);
        float var = t2 * (1.f/D_) - mu*mu;
        stats[0] = mu; stats[1] = rsqrtf(var + 1e-5f);
    }
    __syncthreads();
    float mu = stats[0], rstd = stats[1];
    for (int i = tid; i < D_; i += 256)
        hres[(size_t)row*D_+i] = (xs[i]-mu)*rstd*g[i] + bta[i];
}

// ---------------- log_softmax over V, in-place -------------------------------
__global__ void logsoftmax_kernel(float* __restrict__ out) {
    const int row = blockIdx.x;
    const int tid = threadIdx.x;   // 256
    float* p = out + (size_t)row * V_;
    __shared__ float rbuf[8];
    __shared__ float smax, slse;

    float lmax = -1e30f;
    for (int i = tid; i < V_; i += 256) lmax = fmaxf(lmax, p[i]);
#pragma unroll
    for (int off = 16; off; off >>= 1)
        lmax = fmaxf(lmax, __shfl_down_sync(0xffffffffu, lmax, off));
    if ((tid & 31) == 0) rbuf[tid>>5] = lmax;
    __syncthreads();
    if (tid == 0) {
        float mtot = -1e30f;
        for (int w = 0; w < 8; w++) mtot = fmaxf(mtot, rbuf[w]);
        smax = mtot;
    }
    __syncthreads();
    float mx = smax;

    float lsum = 0.f;
    for (int i = tid; i < V_; i += 256) lsum += __expf(p[i] - mx);
#pragma unroll
    for (int off = 16; off; off >>= 1)
        lsum += __shfl_down_sync(0xffffffffu, lsum, off);
    if ((tid & 31) == 0) rbuf[tid>>5] = lsum;
    __syncthreads();
    if (tid == 0) {
        float stot = 0.f;
        for (int w = 0; w < 8; w++) stot += rbuf[w];
        slse = logf(stot) + mx;
    }
    __syncthreads();
    float lse = slse;
    for (int i = tid; i < V_; i += 256) p[i] = p[i] - lse;
}

// ---------------- host-side helpers ------------------------------------------
static inline void gemm(const float* A, const float* B, const float* bias, float* C,
                        int M, int N, int K, bool relu) {
    dim3 g(N/BN, M/BM);
    if (relu) gemm_tc_kernel<true ><<<g, 128, GEMM_SMEM>>>(A, B, bias, C, M, N, K);
    else      gemm_tc_kernel<false><<<g, 128, GEMM_SMEM>>>(A, B, bias, C, M, N, K);
}

extern "C" void kernel_launch(void* const* d_in, const int* in_sizes, int n_in,
                              void* d_out, int out_size) {
    const int*   x    = (const int*)  d_in[0];
    const float* tok  = (const float*)d_in[1];
    const float* pos  = (const float*)d_in[2];
    const float* wq   = (const float*)d_in[3];
    const float* bq   = (const float*)d_in[4];
    const float* wk   = (const float*)d_in[5];
    const float* bk   = (const float*)d_in[6];
    const float* wv   = (const float*)d_in[7];
    const float* bv   = (const float*)d_in[8];
    const float* wo   = (const float*)d_in[9];
    const float* bo   = (const float*)d_in[10];
    const float* ln1g = (const float*)d_in[11];
    const float* ln1b = (const float*)d_in[12];
    const float* w1   = (const float*)d_in[13];
    const float* b1   = (const float*)d_in[14];
    const float* w2   = (const float*)d_in[15];
    const float* b2   = (const float*)d_in[16];
    const float* ln2g = (const float*)d_in[17];
    const float* ln2b = (const float*)d_in[18];
    const float* wout = (const float*)d_in[19];
    const float* bout = (const float*)d_in[20];
    float* out = (float*)d_out;

    cudaFuncSetAttribute(gemm_tc_kernel<true >, cudaFuncAttributeMaxDynamicSharedMemorySize, GEMM_SMEM);
    cudaFuncSetAttribute(gemm_tc_kernel<false>, cudaFuncAttributeMaxDynamicSharedMemorySize, GEMM_SMEM);

    float *Wqkv, *bqkv, *h, *qkv, *att, *tmp, *ff;
    cudaGetSymbolAddress((void**)&Wqkv, g_Wqkv);
    cudaGetSymbolAddress((void**)&bqkv, g_bqkv);
    cudaGetSymbolAddress((void**)&h,    g_h);
    cudaGetSymbolAddress((void**)&qkv,  g_qkv);
    cudaGetSymbolAddress((void**)&att,  g_att);
    cudaGetSymbolAddress((void**)&tmp,  g_tmp);
    cudaGetSymbolAddress((void**)&ff,   g_ff);

    // pack qkv weights/biases
    {
        int n = L_*D_*QKVW;
        pack_qkv_kernel<<<(n + 255)/256, 256>>>(wq, wk, wv, Wqkv);
        int nb = L_*QKVW;
        pack_bias_kernel<<<(nb + 255)/256, 256>>>(bq, bk, bv, bqkv);
    }

    // embedding
    embed_kernel<<<(ROWS*D_ + 255)/256, 256>>>(x, tok, pos, h);

    for (int l = 0; l < L_; l++) {
        gemm(h, Wqkv + (size_t)l*D_*QKVW, bqkv + (size_t)l*QKVW, qkv, ROWS, QKVW, D_, false);

        dim3 ag(S_/128, B_*H_);
        attn_kernel<<<ag, 128>>>(qkv, att);

        gemm(att, wo + (size_t)l*D_*D_, bo + (size_t)l*D_, tmp, ROWS, D_, D_, false);
        add_ln_kernel<<<ROWS, 256>>>(tmp, h, ln1g + (size_t)l*D_, ln1b + (size_t)l*D_);

        gemm(h,  w1 + (size_t)l*D_*FF_, b1 + (size_t)l*FF_, ff,  ROWS, FF_, D_, true);
        gemm(ff, w2 + (size_t)l*FF_*D_, b2 + (size_t)l*D_,  tmp, ROWS, D_,  FF_, false);
        add_ln_kernel<<<ROWS, 256>>>(tmp, h, ln2g + (size_t)l*D_, ln2b + (size_t)l*D_);
    }

    // final vocab projection + log_softmax (in-place on d_out)
    gemm(h, wout, bout, out, ROWS, V_, D_, false);
    logsoftmax_kernel<<<ROWS, 256>>>(out);
}

// round 11
// speedup vs baseline: 1.3771x; 1.3437x over previous
#include <cuda_runtime.h>
#include <math.h>
#include <stdint.h>

// Model dims (fixed by the problem)
#define L_  8
#define H_  16
#define D_  1024
#define DH_ 64
#define FF_ 4096
#define V_  32000
#define S_  1024
#define B_  2
#define ROWS (B_*S_)   // 2048
#define QKVW (3*D_)    // 3072

// ---------------- scratch (static device globals; no allocation allowed) ----
__device__ float g_Wqkv[L_*D_*QKVW];   // packed [L][D][3072] (q|k|v, head-concat)
__device__ float g_bqkv[L_*QKVW];
__device__ float g_h  [ROWS*D_];
__device__ float g_qkv[ROWS*QKVW];
__device__ float g_att[ROWS*D_];
__device__ float g_tmp[ROWS*D_];
__device__ float g_ff [ROWS*FF_];

// ---------------- pack wq/wk/wv -> [L][D][3072] ------------------------------
__global__ void pack_qkv_kernel(const float* __restrict__ wq, const float* __restrict__ wk,
                                const float* __restrict__ wv, float* __restrict__ W) {
    int i = blockIdx.x * blockDim.x + threadIdx.x;
    if (i >= L_*D_*QKVW) return;
    int l = i / (D_*QKVW);
    int r = i - l*(D_*QKVW);
    int d = r / QKVW;
    int n = r - d*QKVW;
    int sect = n >> 10;         // 0:q 1:k 2:v
    int hn   = n & 1023;
    int h    = hn >> 6;
    int e    = hn & 63;
    const float* src = (sect == 0) ? wq : (sect == 1 ? wk : wv);
    W[i] = src[(((size_t)l*H_ + h)*D_ + d)*DH_ + e];
}

__global__ void pack_bias_kernel(const float* __restrict__ bq, const float* __restrict__ bk,
                                 const float* __restrict__ bv, float* __restrict__ bias) {
    int i = blockIdx.x * blockDim.x + threadIdx.x;
    if (i >= L_*QKVW) return;
    int l = i / QKVW;
    int n = i - l*QKVW;
    int sect = n >> 10;
    int hn   = n & 1023;
    const float* src = (sect == 0) ? bq : (sect == 1 ? bk : bv);
    bias[i] = src[(size_t)l*D_ + hn];
}

// ---------------- embedding: h = tok_emb[x] + pos_emb ----------------------
__global__ void embed_kernel(const int* __restrict__ x, const float* __restrict__ tok,
                             const float* __restrict__ pos, float* __restrict__ out) {
    int i = blockIdx.x * blockDim.x + threadIdx.x;
    if (i >= ROWS*D_) return;
    int bs = i / D_;
    int d  = i - bs*D_;
    int s  = bs & (S_-1);
    int t  = x[bs];
    out[i] = tok[(size_t)t*D_ + d] + pos[(size_t)s*D_ + d];
}

#define CP16(dst_u32, src_ptr) \
    asm volatile("cp.async.cg.shared.global [%0], [%1], 16;\n" :: "r"(dst_u32), "l"(src_ptr))

__device__ __forceinline__ void mma_tf32(float c[4], const uint32_t a[4], const uint32_t b[2]) {
    asm volatile(
        "mma.sync.aligned.m16n8k8.row.col.f32.tf32.tf32.f32 "
        "{%0,%1,%2,%3}, {%4,%5,%6,%7}, {%8,%9}, {%0,%1,%2,%3};\n"
        : "+f"(c[0]), "+f"(c[1]), "+f"(c[2]), "+f"(c[3])
        : "r"(a[0]), "r"(a[1]), "r"(a[2]), "r"(a[3]), "r"(b[0]), "r"(b[1]));
}

// ---------------- tf32 tensor-core GEMM:  C = A[MxK] @ B[KxN] + bias --------
// 128x128 CTA tile, BK=32, 128 threads (4 warps, each 64x64),
// mma.sync.m16n8k8 tf32, 2-stage cp.async pipeline, 3 CTAs/SM.
#define BM 128
#define BN 128
#define BK 32
#define AS_STRIDE 36
#define BS_STRIDE 136
#define AS_STAGE (BM*AS_STRIDE)          // 4608 floats
#define BS_STAGE (BK*BS_STRIDE)          // 4352 floats
#define GEMM_SMEM ((2*(AS_STAGE + BS_STAGE))*4)   // 71680 bytes

template<bool RELU>
__global__ __launch_bounds__(128, 3)
void gemm_tc_kernel(const float* __restrict__ A, const float* __restrict__ B,
                    const float* __restrict__ bias, float* __restrict__ C,
                    int M, int N, int K) {
    extern __shared__ float sm[];
    float* AsBase = sm;                      // [2][BM][36]
    float* BsBase = sm + 2*AS_STAGE;         // [2][BK][136]

    const int tid   = threadIdx.x;
    const int warp  = tid >> 5;
    const int lane  = tid & 31;
    const int warpM = warp >> 1;        // 0..1 -> 64-row slab
    const int warpN = warp & 1;         // 0..1 -> 64-col slab
    const int gid   = lane >> 2;        // 0..7
    const int tig   = lane & 3;         // 0..3

    const int bm = blockIdx.y * BM;
    const int bn = blockIdx.x * BN;

    float acc[4][8][4];
#pragma unroll
    for (int mt = 0; mt < 4; mt++)
#pragma unroll
        for (int nt = 0; nt < 8; nt++)
#pragma unroll
            for (int i = 0; i < 4; i++) acc[mt][nt][i] = 0.f;

    const int KT = K / BK;

    auto copy_tile = [&](int k0, int st) {
        float* As = AsBase + st*AS_STAGE;
        float* Bs = BsBase + st*BS_STAGE;
#pragma unroll
        for (int i = 0; i < 8; i++) {
            int idx = tid + i*128;
            int row = idx >> 3;
            int kc  = (idx & 7) << 2;
            const float* src = A + (size_t)(bm + row)*K + k0 + kc;
            uint32_t dst = (uint32_t)__cvta_generic_to_shared(As + row*AS_STRIDE + kc);
            CP16(dst, src);
        }
#pragma unroll
        for (int i = 0; i < 8; i++) {
            int idx = tid + i*128;
            int row = idx >> 5;
            int nc  = (idx & 31) << 2;
            const float* src = B + (size_t)(k0 + row)*N + bn + nc;
            uint32_t dst = (uint32_t)__cvta_generic_to_shared(Bs + row*BS_STRIDE + nc);
            CP16(dst, src);
        }
        asm volatile("cp.async.commit_group;\n");
    };

    copy_tile(0, 0);

    for (int s = 0; s < KT; s++) {
        const int st = s & 1;
        asm volatile("cp.async.wait_group 0;\n");
        __syncthreads();
        if (s + 1 < KT) copy_tile((s + 1) * BK, st ^ 1);

        const float* As = AsBase + st*AS_STAGE;
        const float* Bs = BsBase + st*BS_STAGE;
#pragma unroll
        for (int kk = 0; kk < 4; kk++) {
            const int kb = kk * 8;
            uint32_t af[4][4];
#pragma unroll
            for (int mt = 0; mt < 4; mt++) {
                int r0 = warpM*64 + mt*16 + gid;
                af[mt][0] = __float_as_uint(As[(r0    )*AS_STRIDE + kb + tig    ]);
                af[mt][1] = __float_as_uint(As[(r0 + 8)*AS_STRIDE + kb + tig    ]);
                af[mt][2] = __float_as_uint(As[(r0    )*AS_STRIDE + kb + tig + 4]);
                af[mt][3] = __float_as_uint(As[(r0 + 8)*AS_STRIDE + kb + tig + 4]);
            }
#pragma unroll
            for (int nt = 0; nt < 8; nt++) {
                int c0 = warpN*64 + nt*8 + gid;
                uint32_t bf[2];
                bf[0] = __float_as_uint(Bs[(kb + tig    )*BS_STRIDE + c0]);
                bf[1] = __float_as_uint(Bs[(kb + tig + 4)*BS_STRIDE + c0]);
#pragma unroll
                for (int mt = 0; mt < 4; mt++) mma_tf32(acc[mt][nt], af[mt], bf);
            }
        }
        __syncthreads();
    }

#pragma unroll
    for (int mt = 0; mt < 4; mt++) {
#pragma unroll
        for (int nt = 0; nt < 8; nt++) {
            int row = bm + warpM*64 + mt*16 + gid;
            int col = bn + warpN*64 + nt*8 + tig*2;
            float b0 = bias[col], b1 = bias[col + 1];
            float v0 = acc[mt][nt][0] + b0;
            float v1 = acc[mt][nt][1] + b1;
            float v2 = acc[mt][nt][2] + b0;
            float v3 = acc[mt][nt][3] + b1;
            if (RELU) {
                v0 = fmaxf(v0, 0.f); v1 = fmaxf(v1, 0.f);
                v2 = fmaxf(v2, 0.f); v3 = fmaxf(v3, 0.f);
            }
            *(float2*)(C + (size_t)row*N + col)       = make_float2(v0, v1);
            *(float2*)(C + (size_t)(row + 8)*N + col) = make_float2(v2, v3);
        }
    }
}

// ---------------- tensor-core causal flash attention ------------------------
// grid: (S/128, B*H), 128 threads (4 warps). Each warp: 32 query rows.
// Per 64-key tile: QK^T (mma, K^T in smem), online softmax (C-frag layout),
// P via smem, PV (mma, V as-is in smem). Q pre-scaled, kept in A-frags.
#define ATS 72                      // smem stride: B-frag LDS bank = 8*tig+gid (bijective)
#define ATT_SMEM ((64*ATS + 64*ATS + 128*ATS)*4)   // Ks + Vs + Ps = 73728 B

__global__ __launch_bounds__(128, 2)
void attn_tc_kernel(const float* __restrict__ qkv, float* __restrict__ o) {
    extern __shared__ float asm_[];
    float* Ks = asm_;                // [64 dims][ATS]  (K transposed)
    float* Vs = asm_ + 64*ATS;       // [64 keys][ATS]
    float* Ps = asm_ + 128*ATS;      // [128 rows][ATS]

    const int tid  = threadIdx.x;
    const int warp = tid >> 5;
    const int lane = tid & 31;
    const int gid  = lane >> 2;      // 0..7
    const int tig  = lane & 3;       // 0..3
    const int q0   = blockIdx.x * 128;
    const int bh   = blockIdx.y;
    const int b    = bh >> 4;
    const int h    = bh & 15;
    const int wr0  = warp * 32;      // warp's local query-row base

    // ---- load Q fragments once (pre-scaled by 1/sqrt(64) = 0.125, exact) ----
    uint32_t qa[2][8][4];
#pragma unroll
    for (int mt = 0; mt < 2; mt++) {
        int r1 = q0 + wr0 + mt*16 + gid;
        const float* q1 = qkv + (size_t)(b*S_ + r1)*QKVW + h*DH_;
        const float* q2 = q1 + (size_t)8*QKVW;
#pragma unroll
        for (int k8 = 0; k8 < 8; k8++) {
            qa[mt][k8][0] = __float_as_uint(q1[k8*8 + tig    ] * 0.125f);
            qa[mt][k8][1] = __float_as_uint(q2[k8*8 + tig    ] * 0.125f);
            qa[mt][k8][2] = __float_as_uint(q1[k8*8 + tig + 4] * 0.125f);
            qa[mt][k8][3] = __float_as_uint(q2[k8*8 + tig + 4] * 0.125f);
        }
    }

    float of[2][8][4];
#pragma unroll
    for (int mt = 0; mt < 2; mt++)
#pragma unroll
        for (int nt = 0; nt < 8; nt++)
#pragma unroll
            for (int i = 0; i < 4; i++) of[mt][nt][i] = 0.f;
    float m_r[2][2], l_r[2][2];
#pragma unroll
    for (int mt = 0; mt < 2; mt++) { m_r[mt][0] = m_r[mt][1] = -1e30f; l_r[mt][0] = l_r[mt][1] = 0.f; }

    const int ntiles = (q0 + 128) >> 6;   // 64-key tiles (causal bound)

    for (int kt = 0; kt < ntiles; kt++) {
        const int kb0 = kt << 6;
        __syncthreads();   // previous tile's PV done -> Ks/Vs reusable

        // K tile: load [64 keys][64 dims], store transposed Ks[dim][key]
        {
            int key  = tid & 63;
            int half = tid >> 6;            // 0..1 -> dims 0-31 / 32-63
            const float* kr = qkv + (size_t)(b*S_ + kb0 + key)*QKVW + D_ + h*DH_ + half*32;
#pragma unroll
            for (int j = 0; j < 8; j++) {
                float4 kv4 = *(const float4*)(kr + j*4);
                int c = half*32 + j*4;
                Ks[(c+0)*ATS + key] = kv4.x;
                Ks[(c+1)*ATS + key] = kv4.y;
                Ks[(c+2)*ATS + key] = kv4.z;
                Ks[(c+3)*ATS + key] = kv4.w;
            }
        }
        // V tile: [64 keys][64 dims] as-is
#pragma unroll
        for (int i = 0; i < 8; i++) {
            int idx = tid + i*128;
            int row = idx >> 4;
            int c4  = (idx & 15) << 2;
            const float* vr = qkv + (size_t)(b*S_ + kb0 + row)*QKVW + 2*D_ + h*DH_ + c4;
            *(float4*)(Vs + row*ATS + c4) = *(const float4*)vr;
        }
        __syncthreads();

        // ---- QK^T ----
        float sc[2][8][4];
#pragma unroll
        for (int mt = 0; mt < 2; mt++)
#pragma unroll
            for (int nt = 0; nt < 8; nt++)
#pragma unroll
                for (int i = 0; i < 4; i++) sc[mt][nt][i] = 0.f;
#pragma unroll
        for (int k8 = 0; k8 < 8; k8++) {
#pragma unroll
            for (int nt = 0; nt < 8; nt++) {
                uint32_t bf[2];
                bf[0] = __float_as_uint(Ks[(k8*8 + tig    )*ATS + nt*8 + gid]);
                bf[1] = __float_as_uint(Ks[(k8*8 + tig + 4)*ATS + nt*8 + gid]);
                mma_tf32(sc[0][nt], qa[0][k8], bf);
                mma_tf32(sc[1][nt], qa[1][k8], bf);
            }
        }

        // ---- causal mask + online softmax (rows r1 = c0/c1, r2 = c2/c3) ----
#pragma unroll
        for (int mt = 0; mt < 2; mt++) {
            int r1 = q0 + wr0 + mt*16 + gid;
            int r2 = r1 + 8;
            // mask
#pragma unroll
            for (int nt = 0; nt < 8; nt++) {
                int c0 = kb0 + nt*8 + tig*2;
                if (c0     > r1) sc[mt][nt][0] = -1e30f;
                if (c0 + 1 > r1) sc[mt][nt][1] = -1e30f;
                if (c0     > r2) sc[mt][nt][2] = -1e30f;
                if (c0 + 1 > r2) sc[mt][nt][3] = -1e30f;
            }
            // row max (across nt, then across tig lanes)
            float t1 = -1e30f, t2 = -1e30f;
#pragma unroll
            for (int nt = 0; nt < 8; nt++) {
                t1 = fmaxf(t1, fmaxf(sc[mt][nt][0], sc[mt][nt][1]));
                t2 = fmaxf(t2, fmaxf(sc[mt][nt][2], sc[mt][nt][3]));
            }
            t1 = fmaxf(t1, __shfl_xor_sync(0xffffffffu, t1, 1));
            t1 = fmaxf(t1, __shfl_xor_sync(0xffffffffu, t1, 2));
            t2 = fmaxf(t2, __shfl_xor_sync(0xffffffffu, t2, 1));
            t2 = fmaxf(t2, __shfl_xor_sync(0xffffffffu, t2, 2));
            float mn1 = fmaxf(m_r[mt][0], t1);
            float mn2 = fmaxf(m_r[mt][1], t2);
            float co1 = __expf(m_r[mt][0] - mn1);
            float co2 = __expf(m_r[mt][1] - mn2);
            // exp + partial sums + write P
            float s1 = 0.f, s2 = 0.f;
            int lr = wr0 + mt*16 + gid;
#pragma unroll
            for (int nt = 0; nt < 8; nt++) {
                float p0 = __expf(sc[mt][nt][0] - mn1);
                float p1 = __expf(sc[mt][nt][1] - mn1);
                float p2 = __expf(sc[mt][nt][2] - mn2);
                float p3 = __expf(sc[mt][nt][3] - mn2);
                s1 += p0 + p1; s2 += p2 + p3;
                *(float2*)(Ps + lr*ATS + nt*8 + tig*2)       = make_float2(p0, p1);
                *(float2*)(Ps + (lr + 8)*ATS + nt*8 + tig*2) = make_float2(p2, p3);
            }
            s1 += __shfl_xor_sync(0xffffffffu, s1, 1);
            s1 += __shfl_xor_sync(0xffffffffu, s1, 2);
            s2 += __shfl_xor_sync(0xffffffffu, s2, 1);
            s2 += __shfl_xor_sync(0xffffffffu, s2, 2);
            l_r[mt][0] = l_r[mt][0]*co1 + s1;
            l_r[mt][1] = l_r[mt][1]*co2 + s2;
            m_r[mt][0] = mn1; m_r[mt][1] = mn2;
            // rescale O accumulator
#pragma unroll
            for (int nt = 0; nt < 8; nt++) {
                of[mt][nt][0] *= co1; of[mt][nt][1] *= co1;
                of[mt][nt][2] *= co2; of[mt][nt][3] *= co2;
            }
        }
        __syncwarp();   // Ps rows are warp-private: write -> read ordering

        // ---- PV ----
#pragma unroll
        for (int k8 = 0; k8 < 8; k8++) {
            uint32_t pa[2][4];
#pragma unroll
            for (int mt = 0; mt < 2; mt++) {
                int lr = wr0 + mt*16 + gid;
                pa[mt][0] = __float_as_uint(Ps[(lr    )*ATS + k8*8 + tig    ]);
                pa[mt][1] = __float_as_uint(Ps[(lr + 8)*ATS + k8*8 + tig    ]);
                pa[mt][2] = __float_as_uint(Ps[(lr    )*ATS + k8*8 + tig + 4]);
                pa[mt][3] = __float_as_uint(Ps[(lr + 8)*ATS + k8*8 + tig + 4]);
            }
#pragma unroll
            for (int nt = 0; nt < 8; nt++) {
                uint32_t bf[2];
                bf[0] = __float_as_uint(Vs[(k8*8 + tig    )*ATS + nt*8 + gid]);
                bf[1] = __float_as_uint(Vs[(k8*8 + tig + 4)*ATS + nt*8 + gid]);
                mma_tf32(of[0][nt], pa[0], bf);
                mma_tf32(of[1][nt], pa[1], bf);
            }
        }
    }

    // ---- epilogue: normalize and store ----
#pragma unroll
    for (int mt = 0; mt < 2; mt++) {
        int r1 = q0 + wr0 + mt*16 + gid;
        float inv1 = 1.f / l_r[mt][0];
        float inv2 = 1.f / l_r[mt][1];
        float* o1 = o + (size_t)(b*S_ + r1)*D_ + h*DH_;
        float* o2 = o1 + (size_t)8*D_;
#pragma unroll
        for (int nt = 0; nt < 8; nt++) {
            int c = nt*8 + tig*2;
            *(float2*)(o1 + c) = make_float2(of[mt][nt][0]*inv1, of[mt][nt][1]*inv1);
            *(float2*)(o2 + c) = make_float2(of[mt][nt][2]*inv2, of[mt][nt][3]*inv2);
        }
    }
}

// ---------------- residual add + LayerNorm (in-place into hres) -------------
__global__ void add_ln_kernel(const float* __restrict__ a, float* __restrict__ hres,
                              const float* __restrict__ g, const float* __restrict__ bta) {
    const int row = blockIdx.x;
    const int tid = threadIdx.x;   // 256
    __shared__ float xs[D_];
    __shared__ float rbuf[2][8];
    __shared__ float stats[2];

    float s1 = 0.f, s2 = 0.f;
    for (int i = tid; i < D_; i += 256) {
        float x = a[(size_t)row*D_+i] + hres[(size_t)row*D_+i];
        xs[i] = x; s1 += x; s2 += x*x;
    }
#pragma unroll
    for (int off = 16; off; off >>= 1) {
        s1 += __shfl_down_sync(0xffffffffu, s1, off);
        s2 += __shfl_down_sync(0xffffffffu, s2, off);
    }
    if ((tid & 31) == 0) { rbuf[0][tid>>5] = s1; rbuf[1][tid>>5] = s2; }
    __syncthreads();
    if (tid == 0) {
        float t1 = 0.f, t2 = 0.f;
        for (int w = 0; w < 8; w++) { t1 += rbuf[0][w]; t2 += rbuf[1][w]; }
        float mu  = t1 * (1.f/D_);
        float var = t2 * (1.f/D_) - mu*mu;
        stats[0] = mu; stats[1] = rsqrtf(var + 1e-5f);
    }
    __syncthreads();
    float mu = stats[0], rstd = stats[1];
    for (int i = tid; i < D_; i += 256)
        hres[(size_t)row*D_+i] = (xs[i]-mu)*rstd*g[i] + bta[i];
}

// ---------------- log_softmax over V, in-place -------------------------------
__global__ void logsoftmax_kernel(float* __restrict__ out) {
    const int row = blockIdx.x;
    const int tid = threadIdx.x;   // 256
    float* p = out + (size_t)row * V_;
    __shared__ float rbuf[8];
    __shared__ float smax, slse;

    float lmax = -1e30f;
    for (int i = tid; i < V_; i += 256) lmax = fmaxf(lmax, p[i]);
#pragma unroll
    for (int off = 16; off; off >>= 1)
        lmax = fmaxf(lmax, __shfl_down_sync(0xffffffffu, lmax, off));
    if ((tid & 31) == 0) rbuf[tid>>5] = lmax;
    __syncthreads();
    if (tid == 0) {
        float mtot = -1e30f;
        for (int w = 0; w < 8; w++) mtot = fmaxf(mtot, rbuf[w]);
        smax = mtot;
    }
    __syncthreads();
    float mx = smax;

    float lsum = 0.f;
    for (int i = tid; i < V_; i += 256) lsum += __expf(p[i] - mx);
#pragma unroll
    for (int off = 16; off; off >>= 1)
        lsum += __shfl_down_sync(0xffffffffu, lsum, off);
    if ((tid & 31) == 0) rbuf[tid>>5] = lsum;
    __syncthreads();
    if (tid == 0) {
        float stot = 0.f;
        for (int w = 0; w < 8; w++) stot += rbuf[w];
        slse = logf(stot) + mx;
    }
    __syncthreads();
    float lse = slse;
    for (int i = tid; i < V_; i += 256) p[i] = p[i] - lse;
}

// ---------------- host-side helpers ------------------------------------------
static inline void gemm(const float* A, const float* B, const float* bias, float* C,
                        int M, int N, int K, bool relu) {
    dim3 g(N/BN, M/BM);
    if (relu) gemm_tc_kernel<true ><<<g, 128, GEMM_SMEM>>>(A, B, bias, C, M, N, K);
    else      gemm_tc_kernel<false><<<g, 128, GEMM_SMEM>>>(A, B, bias, C, M, N, K);
}

extern "C" void kernel_launch(void* const* d_in, const int* in_sizes, int n_in,
                              void* d_out, int out_size) {
    const int*   x    = (const int*)  d_in[0];
    const float* tok  = (const float*)d_in[1];
    const float* pos  = (const float*)d_in[2];
    const float* wq   = (const float*)d_in[3];
    const float* bq   = (const float*)d_in[4];
    const float* wk   = (const float*)d_in[5];
    const float* bk   = (const float*)d_in[6];
    const float* wv   = (const float*)d_in[7];
    const float* bv   = (const float*)d_in[8];
    const float* wo   = (const float*)d_in[9];
    const float* bo   = (const float*)d_in[10];
    const float* ln1g = (const float*)d_in[11];
    const float* ln1b = (const float*)d_in[12];
    const float* w1   = (const float*)d_in[13];
    const float* b1   = (const float*)d_in[14];
    const float* w2   = (const float*)d_in[15];
    const float* b2   = (const float*)d_in[16];
    const float* ln2g = (const float*)d_in[17];
    const float* ln2b = (const float*)d_in[18];
    const float* wout = (const float*)d_in[19];
    const float* bout = (const float*)d_in[20];
    float* out = (float*)d_out;

    cudaFuncSetAttribute(gemm_tc_kernel<true >, cudaFuncAttributeMaxDynamicSharedMemorySize, GEMM_SMEM);
    cudaFuncSetAttribute(gemm_tc_kernel<false>, cudaFuncAttributeMaxDynamicSharedMemorySize, GEMM_SMEM);
    cudaFuncSetAttribute(attn_tc_kernel, cudaFuncAttributeMaxDynamicSharedMemorySize, ATT_SMEM);

    float *Wqkv, *bqkv, *h, *qkv, *att, *tmp, *ff;
    cudaGetSymbolAddress((void**)&Wqkv, g_Wqkv);
    cudaGetSymbolAddress((void**)&bqkv, g_bqkv);
    cudaGetSymbolAddress((void**)&h,    g_h);
    cudaGetSymbolAddress((void**)&qkv,  g_qkv);
    cudaGetSymbolAddress((void**)&att,  g_att);
    cudaGetSymbolAddress((void**)&tmp,  g_tmp);
    cudaGetSymbolAddress((void**)&ff,   g_ff);

    // pack qkv weights/biases
    {
        int n = L_*D_*QKVW;
        pack_qkv_kernel<<<(n + 255)/256, 256>>>(wq, wk, wv, Wqkv);
        int nb = L_*QKVW;
        pack_bias_kernel<<<(nb + 255)/256, 256>>>(bq, bk, bv, bqkv);
    }

    // embedding
    embed_kernel<<<(ROWS*D_ + 255)/256, 256>>>(x, tok, pos, h);

    for (int l = 0; l < L_; l++) {
        gemm(h, Wqkv + (size_t)l*D_*QKVW, bqkv + (size_t)l*QKVW, qkv, ROWS, QKVW, D_, false);

        dim3 ag(S_/128, B_*H_);
        attn_tc_kernel<<<ag, 128, ATT_SMEM>>>(qkv, att);

        gemm(att, wo + (size_t)l*D_*D_, bo + (size_t)l*D_, tmp, ROWS, D_, D_, false);
        add_ln_kernel<<<ROWS, 256>>>(tmp, h, ln1g + (size_t)l*D_, ln1b + (size_t)l*D_);

        gemm(h,  w1 + (size_t)l*D_*FF_, b1 + (size_t)l*FF_, ff,  ROWS, FF_, D_, true);
        gemm(ff, w2 + (size_t)l*FF_*D_, b2 + (size_t)l*D_,  tmp, ROWS, D_,  FF_, false);
        add_ln_kernel<<<ROWS, 256>>>(tmp, h, ln2g + (size_t)l*D_, ln2b + (size_t)l*D_);
    }

    // final vocab projection + log_softmax (in-place on d_out)
    gemm(h, wout, bout, out, ROWS, V_, D_, false);
    logsoftmax_kernel<<<ROWS, 256>>>(out);
}

// round 14
// speedup vs baseline: 2.0143x; 1.4627x over previous
#include <cuda_runtime.h>
#include <cuda_fp16.h>
#include <math.h>
#include <stdint.h>

// Model dims (fixed by the problem)
#define L_  8
#define H_  16
#define D_  1024
#define DH_ 64
#define FF_ 4096
#define V_  32000
#define S_  1024
#define B_  2
#define ROWS (B_*S_)   // 2048
#define QKVW (3*D_)    // 3072

// ---------------- scratch (static device globals; no allocation allowed) ----
// fp16 transposed weights: [N][K] so mma.row.col B-frag = one 32-bit LDS
__device__ __half g_WqkvT[L_*QKVW*D_];
__device__ __half g_WoT [L_*D_*D_];
__device__ __half g_W1T [L_*FF_*D_];
__device__ __half g_W2T [L_*D_*FF_];
__device__ __half g_WoutT[V_*D_];
__device__ float  g_bqkv[L_*QKVW];
// activations
__device__ float  g_h   [ROWS*D_];     // fp32 residual stream
__device__ __half g_h16 [ROWS*D_];     // fp16 copy for GEMM A
__device__ __half g_qkv16[ROWS*QKVW];
__device__ __half g_att16[ROWS*D_];
__device__ __half g_ff16 [ROWS*FF_];
__device__ float  g_tmp [ROWS*D_];

// ---------------- weight conversion/transpose kernels ------------------------
// pack wq/wk/wv [L,H,D,DH] -> fp16 [L][3072 n][1024 k]
__global__ void pack_qkv_t_kernel(const float* __restrict__ wq, const float* __restrict__ wk,
                                  const float* __restrict__ wv, __half* __restrict__ W) {
    int i = blockIdx.x * blockDim.x + threadIdx.x;
    if (i >= L_*QKVW*D_) return;
    int l = i / (QKVW*D_);
    int r = i - l*(QKVW*D_);
    int n = r / D_;
    int k = r - n*D_;
    int sect = n >> 10;
    int hn   = n & 1023;
    int hd   = hn >> 6;
    int e    = hn & 63;
    const float* src = (sect == 0) ? wq : (sect == 1 ? wk : wv);
    W[i] = __float2half_rn(src[(((size_t)l*H_ + hd)*D_ + k)*DH_ + e]);
}

__global__ void pack_bias_kernel(const float* __restrict__ bq, const float* __restrict__ bk,
                                 const float* __restrict__ bv, float* __restrict__ bias) {
    int i = blockIdx.x * blockDim.x + threadIdx.x;
    if (i >= L_*QKVW) return;
    int l = i / QKVW;
    int n = i - l*QKVW;
    int sect = n >> 10;
    int hn   = n & 1023;
    const float* src = (sect == 0) ? bq : (sect == 1 ? bk : bv);
    bias[i] = src[(size_t)l*D_ + hn];
}

// batched tiled transpose fp32 [z][P][Q] -> fp16 [z][Q][P]
__global__ void transpose_h_kernel(const float* __restrict__ src, __half* __restrict__ dst,
                                   int P, int Q) {
    __shared__ float t[32][33];
    const size_t off = (size_t)blockIdx.z * P * Q;
    const int p0 = blockIdx.y * 32, q0 = blockIdx.x * 32;
    const int tx = threadIdx.x, ty = threadIdx.y;
#pragma unroll
    for (int j = ty; j < 32; j += 8)
        t[j][tx] = src[off + (size_t)(p0+j)*Q + q0 + tx];
    __syncthreads();
#pragma unroll
    for (int j = ty; j < 32; j += 8)
        dst[off + (size_t)(q0+j)*P + p0 + tx] = __float2half_rn(t[tx][j]);
}

// ---------------- embedding: h = tok_emb[x] + pos_emb (fp32 + fp16) ---------
__global__ void embed_kernel(const int* __restrict__ x, const float* __restrict__ tok,
                             const float* __restrict__ pos, float* __restrict__ out,
                             __half* __restrict__ out16) {
    int i = blockIdx.x * blockDim.x + threadIdx.x;
    if (i >= ROWS*D_) return;
    int bs = i / D_;
    int d  = i - bs*D_;
    int s  = bs & (S_-1);
    int t  = x[bs];
    float v = tok[(size_t)t*D_ + d] + pos[(size_t)s*D_ + d];
    out[i] = v;
    out16[i] = __float2half_rn(v);
}

#define CP16(dst_u32, src_ptr) \
    asm volatile("cp.async.cg.shared.global [%0], [%1], 16;\n" :: "r"(dst_u32), "l"(src_ptr))

__device__ __forceinline__ void mma_f16(float c[4], const uint32_t a[4], const uint32_t b[2]) {
    asm volatile(
        "mma.sync.aligned.m16n8k16.row.col.f32.f16.f16.f32 "
        "{%0,%1,%2,%3}, {%4,%5,%6,%7}, {%8,%9}, {%0,%1,%2,%3};\n"
        : "+f"(c[0]), "+f"(c[1]), "+f"(c[2]), "+f"(c[3])
        : "r"(a[0]), "r"(a[1]), "r"(a[2]), "r"(a[3]), "r"(b[0]), "r"(b[1]));
}

__device__ __forceinline__ void mma_tf32(float c[4], const uint32_t a[4], const uint32_t b[2]) {
    asm volatile(
        "mma.sync.aligned.m16n8k8.row.col.f32.tf32.tf32.f32 "
        "{%0,%1,%2,%3}, {%4,%5,%6,%7}, {%8,%9}, {%0,%1,%2,%3};\n"
        : "+f"(c[0]), "+f"(c[1]), "+f"(c[2]), "+f"(c[3])
        : "r"(a[0]), "r"(a[1]), "r"(a[2]), "r"(a[3]), "r"(b[0]), "r"(b[1]));
}

// ---------------- fp16 tensor-core GEMM:  C = A[MxK] @ Wt[N][K]^T + bias ----
// 128x128 CTA tile, BK=32 (2 k-steps of m16n8k16), 128 threads (4 warps, 64x64),
// 2-stage cp.async, 3 CTAs/SM. Smem stride 20 words: frag LDS bank-bijective.
#define BM 128
#define BN 128
#define BK 32
#define WST 20                              // words (uint32) per row = 32 halves + pad
#define T_STAGE (BM*WST)                    // words per A (or B) stage = 2560
#define GEMM_SMEM (2*2*T_STAGE*4)           // 40960 bytes

template<bool RELU, bool OUT16>
__global__ __launch_bounds__(128, 3)
void gemm_h_kernel(const __half* __restrict__ A, const __half* __restrict__ Bt,
                   const float* __restrict__ bias, void* __restrict__ Cv,
                   int M, int N, int K) {
    extern __shared__ uint32_t smw[];
    uint32_t* AsW = smw;                    // [2][BM][20]
    uint32_t* BsW = smw + 2*T_STAGE;        // [2][BN][20]

    const int tid   = threadIdx.x;
    const int warp  = tid >> 5;
    const int lane  = tid & 31;
    const int warpM = warp >> 1;
    const int warpN = warp & 1;
    const int gid   = lane >> 2;
    const int tig   = lane & 3;

    const int bm = blockIdx.y * BM;
    const int bn = blockIdx.x * BN;

    float acc[4][8][4];
#pragma unroll
    for (int mt = 0; mt < 4; mt++)
#pragma unroll
        for (int nt = 0; nt < 8; nt++)
#pragma unroll
            for (int i = 0; i < 4; i++) acc[mt][nt][i] = 0.f;

    const int KT = K / BK;

    // per stage: A 128 rows x 32 halves (4x16B/row) + B same = 1024 chunks, 8/thread
    auto copy_tile = [&](int k0, int st) {
        uint32_t* As = AsW + st*T_STAGE;
        uint32_t* Bs = BsW + st*T_STAGE;
#pragma unroll
        for (int i = 0; i < 4; i++) {
            int idx = tid + i*128;
            int row = idx >> 2;
            int ch  = idx & 3;
            const __half* src = A + (size_t)(bm + row)*K + k0 + ch*8;
            uint32_t dst = (uint32_t)__cvta_generic_to_shared(As + row*WST + ch*4);
            CP16(dst, src);
        }
#pragma unroll
        for (int i = 0; i < 4; i++) {
            int idx = tid + i*128;
            int row = idx >> 2;
            int ch  = idx & 3;
            const __half* src = Bt + (size_t)(bn + row)*K + k0 + ch*8;
            uint32_t dst = (uint32_t)__cvta_generic_to_shared(Bs + row*WST + ch*4);
            CP16(dst, src);
        }
        asm volatile("cp.async.commit_group;\n");
    };

    copy_tile(0, 0);

    for (int s = 0; s < KT; s++) {
        const int st = s & 1;
        asm volatile("cp.async.wait_group 0;\n");
        __syncthreads();
        if (s + 1 < KT) copy_tile((s + 1) * BK, st ^ 1);

        const uint32_t* As = AsW + st*T_STAGE;
        const uint32_t* Bs = BsW + st*T_STAGE;
#pragma unroll
        for (int kk = 0; kk < 2; kk++) {
            const int kw = kk * 8;
            uint32_t af[4][4];
#pragma unroll
            for (int mt = 0; mt < 4; mt++) {
                int r0 = warpM*64 + mt*16 + gid;
                af[mt][0] = As[(r0    )*WST + kw + tig    ];
                af[mt][1] = As[(r0 + 8)*WST + kw + tig    ];
                af[mt][2] = As[(r0    )*WST + kw + tig + 4];
                af[mt][3] = As[(r0 + 8)*WST + kw + tig + 4];
            }
#pragma unroll
            for (int nt = 0; nt < 8; nt++) {
                int c0 = warpN*64 + nt*8 + gid;
                uint32_t bf[2];
                bf[0] = Bs[c0*WST + kw + tig    ];
                bf[1] = Bs[c0*WST + kw + tig + 4];
#pragma unroll
                for (int mt = 0; mt < 4; mt++) mma_f16(acc[mt][nt], af[mt], bf);
            }
        }
        __syncthreads();
    }

    // epilogue: bias (+relu), fp32 or fp16 stores
#pragma unroll
    for (int mt = 0; mt < 4; mt++) {
#pragma unroll
        for (int nt = 0; nt < 8; nt++) {
            int row = bm + warpM*64 + mt*16 + gid;
            int col = bn + warpN*64 + nt*8 + tig*2;
            float b0 = bias[col], b1 = bias[col + 1];
            float v0 = acc[mt][nt][0] + b0;
            float v1 = acc[mt][nt][1] + b1;
            float v2 = acc[mt][nt][2] + b0;
            float v3 = acc[mt][nt][3] + b1;
            if (RELU) {
                v0 = fmaxf(v0, 0.f); v1 = fmaxf(v1, 0.f);
                v2 = fmaxf(v2, 0.f); v3 = fmaxf(v3, 0.f);
            }
            if (OUT16) {
                __half* C = (__half*)Cv;
                *(__half2*)(C + (size_t)row*N + col)       = __floats2half2_rn(v0, v1);
                *(__half2*)(C + (size_t)(row + 8)*N + col) = __floats2half2_rn(v2, v3);
            } else {
                float* C = (float*)Cv;
                *(float2*)(C + (size_t)row*N + col)       = make_float2(v0, v1);
                *(float2*)(C + (size_t)(row + 8)*N + col) = make_float2(v2, v3);
            }
        }
    }
}

// ---------------- tensor-core causal flash attention (fp16 in/out) ----------
// grid: (S/128, B*H), 128 threads (4 warps), warp = 32 query rows.
#define ATS 72
#define ATT_SMEM ((64*ATS + 64*ATS + 128*ATS)*4)   // 73728 B

__global__ __launch_bounds__(128, 2)
void attn_tc_kernel(const __half* __restrict__ qkv, __half* __restrict__ o) {
    extern __shared__ float asm_[];
    float* Ks = asm_;                // [64 dims][ATS]  (K transposed)
    float* Vs = asm_ + 64*ATS;       // [64 keys][ATS]
    float* Ps = asm_ + 128*ATS;      // [128 rows][ATS]

    const int tid  = threadIdx.x;
    const int warp = tid >> 5;
    const int lane = tid & 31;
    const int gid  = lane >> 2;
    const int tig  = lane & 3;
    const int q0   = blockIdx.x * 128;
    const int bh   = blockIdx.y;
    const int b    = bh >> 4;
    const int h    = bh & 15;
    const int wr0  = warp * 32;

    // ---- load Q fragments once (pre-scaled by 0.125) ----
    uint32_t qa[2][8][4];
#pragma unroll
    for (int mt = 0; mt < 2; mt++) {
        int r1 = q0 + wr0 + mt*16 + gid;
        const __half* q1 = qkv + (size_t)(b*S_ + r1)*QKVW + h*DH_;
        const __half* q2 = q1 + (size_t)8*QKVW;
#pragma unroll
        for (int k8 = 0; k8 < 8; k8++) {
            qa[mt][k8][0] = __float_as_uint(__half2float(q1[k8*8 + tig    ]) * 0.125f);
            qa[mt][k8][1] = __float_as_uint(__half2float(q2[k8*8 + tig    ]) * 0.125f);
            qa[mt][k8][2] = __float_as_uint(__half2float(q1[k8*8 + tig + 4]) * 0.125f);
            qa[mt][k8][3] = __float_as_uint(__half2float(q2[k8*8 + tig + 4]) * 0.125f);
        }
    }

    float of[2][8][4];
#pragma unroll
    for (int mt = 0; mt < 2; mt++)
#pragma unroll
        for (int nt = 0; nt < 8; nt++)
#pragma unroll
            for (int i = 0; i < 4; i++) of[mt][nt][i] = 0.f;
    float m_r[2][2], l_r[2][2];
#pragma unroll
    for (int mt = 0; mt < 2; mt++) { m_r[mt][0] = m_r[mt][1] = -1e30f; l_r[mt][0] = l_r[mt][1] = 0.f; }

    const int ntiles = (q0 + 128) >> 6;

    for (int kt = 0; kt < ntiles; kt++) {
        const int kb0 = kt << 6;
        __syncthreads();

        // K tile: [64 keys][64 dims] fp16 -> transposed fp32 Ks[dim][key]
        {
            int key = tid & 63;
            int hf  = tid >> 6;
            const __half* kr = qkv + (size_t)(b*S_ + kb0 + key)*QKVW + D_ + h*DH_ + hf*32;
#pragma unroll
            for (int j = 0; j < 4; j++) {
                uint4 u = *(const uint4*)(kr + j*8);
                const __half2* hp = (const __half2*)&u;
                int c = hf*32 + j*8;
#pragma unroll
                for (int p = 0; p < 4; p++) {
                    float2 f = __half22float2(hp[p]);
                    Ks[(c + 2*p    )*ATS + key] = f.x;
                    Ks[(c + 2*p + 1)*ATS + key] = f.y;
                }
            }
        }
        // V tile: [64 keys][64 dims] fp16 -> fp32 Vs as-is
#pragma unroll
        for (int i = 0; i < 4; i++) {
            int idx = tid + i*128;
            int row = idx >> 3;
            int c8  = (idx & 7) << 3;
            const __half* vr = qkv + (size_t)(b*S_ + kb0 + row)*QKVW + 2*D_ + h*DH_ + c8;
            uint4 u = *(const uint4*)vr;
            const __half2* hp = (const __half2*)&u;
#pragma unroll
            for (int p = 0; p < 4; p++) {
                float2 f = __half22float2(hp[p]);
                Vs[row*ATS + c8 + 2*p    ] = f.x;
                Vs[row*ATS + c8 + 2*p + 1] = f.y;
            }
        }
        __syncthreads();

        // ---- QK^T ----
        float sc[2][8][4];
#pragma unroll
        for (int mt = 0; mt < 2; mt++)
#pragma unroll
            for (int nt = 0; nt < 8; nt++)
#pragma unroll
                for (int i = 0; i < 4; i++) sc[mt][nt][i] = 0.f;
#pragma unroll
        for (int k8 = 0; k8 < 8; k8++) {
#pragma unroll
            for (int nt = 0; nt < 8; nt++) {
                uint32_t bf[2];
                bf[0] = __float_as_uint(Ks[(k8*8 + tig    )*ATS + nt*8 + gid]);
                bf[1] = __float_as_uint(Ks[(k8*8 + tig + 4)*ATS + nt*8 + gid]);
                mma_tf32(sc[0][nt], qa[0][k8], bf);
                mma_tf32(sc[1][nt], qa[1][k8], bf);
            }
        }

        // ---- causal mask + online softmax ----
#pragma unroll
        for (int mt = 0; mt < 2; mt++) {
            int r1 = q0 + wr0 + mt*16 + gid;
            int r2 = r1 + 8;
#pragma unroll
            for (int nt = 0; nt < 8; nt++) {
                int c0 = kb0 + nt*8 + tig*2;
                if (c0     > r1) sc[mt][nt][0] = -1e30f;
                if (c0 + 1 > r1) sc[mt][nt][1] = -1e30f;
                if (c0     > r2) sc[mt][nt][2] = -1e30f;
                if (c0 + 1 > r2) sc[mt][nt][3] = -1e30f;
            }
            float t1 = -1e30f, t2 = -1e30f;
#pragma unroll
            for (int nt = 0; nt < 8; nt++) {
                t1 = fmaxf(t1, fmaxf(sc[mt][nt][0], sc[mt][nt][1]));
                t2 = fmaxf(t2, fmaxf(sc[mt][nt][2], sc[mt][nt][3]));
            }
            t1 = fmaxf(t1, __shfl_xor_sync(0xffffffffu, t1, 1));
            t1 = fmaxf(t1, __shfl_xor_sync(0xffffffffu, t1, 2));
            t2 = fmaxf(t2, __shfl_xor_sync(0xffffffffu, t2, 1));
            t2 = fmaxf(t2, __shfl_xor_sync(0xffffffffu, t2, 2));
            float mn1 = fmaxf(m_r[mt][0], t1);
            float mn2 = fmaxf(m_r[mt][1], t2);
            float co1 = __expf(m_r[mt][0] - mn1);
            float co2 = __expf(m_r[mt][1] - mn2);
            float s1 = 0.f, s2 = 0.f;
            int lr = wr0 + mt*16 + gid;
#pragma unroll
            for (int nt = 0; nt < 8; nt++) {
                float p0 = __expf(sc[mt][nt][0] - mn1);
                float p1 = __expf(sc[mt][nt][1] - mn1);
                float p2 = __expf(sc[mt][nt][2] - mn2);
                float p3 = __expf(sc[mt][nt][3] - mn2);
                s1 += p0 + p1; s2 += p2 + p3;
                *(float2*)(Ps + lr*ATS + nt*8 + tig*2)       = make_float2(p0, p1);
                *(float2*)(Ps + (lr + 8)*ATS + nt*8 + tig*2) = make_float2(p2, p3);
            }
            s1 += __shfl_xor_sync(0xffffffffu, s1, 1);
            s1 += __shfl_xor_sync(0xffffffffu, s1, 2);
            s2 += __shfl_xor_sync(0xffffffffu, s2, 1);
            s2 += __shfl_xor_sync(0xffffffffu, s2, 2);
            l_r[mt][0] = l_r[mt][0]*co1 + s1;
            l_r[mt][1] = l_r[mt][1]*co2 + s2;
            m_r[mt][0] = mn1; m_r[mt][1] = mn2;
#pragma unroll
            for (int nt = 0; nt < 8; nt++) {
                of[mt][nt][0] *= co1; of[mt][nt][1] *= co1;
                of[mt][nt][2] *= co2; of[mt][nt][3] *= co2;
            }
        }
        __syncwarp();

        // ---- PV ----
#pragma unroll
        for (int k8 = 0; k8 < 8; k8++) {
            uint32_t pa[2][4];
#pragma unroll
            for (int mt = 0; mt < 2; mt++) {
                int lr = wr0 + mt*16 + gid;
                pa[mt][0] = __float_as_uint(Ps[(lr    )*ATS + k8*8 + tig    ]);
                pa[mt][1] = __float_as_uint(Ps[(lr + 8)*ATS + k8*8 + tig    ]);
                pa[mt][2] = __float_as_uint(Ps[(lr    )*ATS + k8*8 + tig + 4]);
                pa[mt][3] = __float_as_uint(Ps[(lr + 8)*ATS + k8*8 + tig + 4]);
            }
#pragma unroll
            for (int nt = 0; nt < 8; nt++) {
                uint32_t bf[2];
                bf[0] = __float_as_uint(Vs[(k8*8 + tig    )*ATS + nt*8 + gid]);
                bf[1] = __float_as_uint(Vs[(k8*8 + tig + 4)*ATS + nt*8 + gid]);
                mma_tf32(of[0][nt], pa[0], bf);
                mma_tf32(of[1][nt], pa[1], bf);
            }
        }
    }

    // ---- epilogue: normalize, store fp16 ----
#pragma unroll
    for (int mt = 0; mt < 2; mt++) {
        int r1 = q0 + wr0 + mt*16 + gid;
        float inv1 = 1.f / l_r[mt][0];
        float inv2 = 1.f / l_r[mt][1];
        __half* o1 = o + (size_t)(b*S_ + r1)*D_ + h*DH_;
        __half* o2 = o1 + (size_t)8*D_;
#pragma unroll
        for (int nt = 0; nt < 8; nt++) {
            int c = nt*8 + tig*2;
            *(__half2*)(o1 + c) = __floats2half2_rn(of[mt][nt][0]*inv1, of[mt][nt][1]*inv1);
            *(__half2*)(o2 + c) = __floats2half2_rn(of[mt][nt][2]*inv2, of[mt][nt][3]*inv2);
        }
    }
}

// ---------------- residual add + LayerNorm (fp32 + fp16 out) ----------------
__global__ void add_ln_kernel(const float* __restrict__ a, float* __restrict__ hres,
                              __half* __restrict__ h16,
                              const float* __restrict__ g, const float* __restrict__ bta) {
    const int row = blockIdx.x;
    const int tid = threadIdx.x;   // 256
    __shared__ float xs[D_];
    __shared__ float rbuf[2][8];
    __shared__ float stats[2];

    float s1 = 0.f, s2 = 0.f;
    for (int i = tid; i < D_; i += 256) {
        float x = a[(size_t)row*D_+i] + hres[(size_t)row*D_+i];
        xs[i] = x; s1 += x; s2 += x*x;
    }
#pragma unroll
    for (int off = 16; off; off >>= 1) {
        s1 += __shfl_down_sync(0xffffffffu, s1, off);
        s2 += __shfl_down_sync(0xffffffffu, s2, off);
    }
    if ((tid & 31) == 0) { rbuf[0][tid>>5] = s1; rbuf[1][tid>>5] = s2; }
    __syncthreads();
    if (tid == 0) {
        float t1 = 0.f, t2 = 0.f;
        for (int w = 0; w < 8; w++) { t1 += rbuf[0][w]; t2 += rbuf[1][w]; }
        float mu  = t1 * (1.f/D_);
        float var = t2 * (1.f/D_) - mu*mu;
        stats[0] = mu; stats[1] = rsqrtf(var + 1e-5f);
    }
    __syncthreads();
    float mu = stats[0], rstd = stats[1];
    for (int i = tid; i < D_; i += 256) {
        float v = (xs[i]-mu)*rstd*g[i] + bta[i];
        hres[(size_t)row*D_+i] = v;
        h16[(size_t)row*D_+i]  = __float2half_rn(v);
    }
}

// ---------------- log_softmax over V, in-place -------------------------------
__global__ void logsoftmax_kernel(float* __restrict__ out) {
    const int row = blockIdx.x;
    const int tid = threadIdx.x;   // 256
    float* p = out + (size_t)row * V_;
    __shared__ float rbuf[8];
    __shared__ float smax, slse;

    float lmax = -1e30f;
    for (int i = tid; i < V_; i += 256) lmax = fmaxf(lmax, p[i]);
#pragma unroll
    for (int off = 16; off; off >>= 1)
        lmax = fmaxf(lmax, __shfl_down_sync(0xffffffffu, lmax, off));
    if ((tid & 31) == 0) rbuf[tid>>5] = lmax;
    __syncthreads();
    if (tid == 0) {
        float mtot = -1e30f;
        for (int w = 0; w < 8; w++) mtot = fmaxf(mtot, rbuf[w]);
        smax = mtot;
    }
    __syncthreads();
    float mx = smax;

    float lsum = 0.f;
    for (int i = tid; i < V_; i += 256) lsum += __expf(p[i] - mx);
#pragma unroll
    for (int off = 16; off; off >>= 1)
        lsum += __shfl_down_sync(0xffffffffu, lsum, off);
    if ((tid & 31) == 0) rbuf[tid>>5] = lsum;
    __syncthreads();
    if (tid == 0) {
        float stot = 0.f;
        for (int w = 0; w < 8; w++) stot += rbuf[w];
        slse = logf(stot) + mx;
    }
    __syncthreads();
    float lse = slse;
    for (int i = tid; i < V_; i += 256) p[i] = p[i] - lse;
}

// ---------------- host-side helpers ------------------------------------------
static inline void gemm_h(const __half* A, const __half* Bt, const float* bias, void* C,
                          int M, int N, int K, bool relu, bool out16) {
    dim3 g(N/BN, M/BM);
    if (out16) {
        if (relu) gemm_h_kernel<true , true ><<<g, 128, GEMM_SMEM>>>(A, Bt, bias, C, M, N, K);
        else      gemm_h_kernel<false, true ><<<g, 128, GEMM_SMEM>>>(A, Bt, bias, C, M, N, K);
    } else {
        if (relu) gemm_h_kernel<true , false><<<g, 128, GEMM_SMEM>>>(A, Bt, bias, C, M, N, K);
        else      gemm_h_kernel<false, false><<<g, 128, GEMM_SMEM>>>(A, Bt, bias, C, M, N, K);
    }
}

extern "C" void kernel_launch(void* const* d_in, const int* in_sizes, int n_in,
                              void* d_out, int out_size) {
    const int*   x    = (const int*)  d_in[0];
    const float* tok  = (const float*)d_in[1];
    const float* pos  = (const float*)d_in[2];
    const float* wq   = (const float*)d_in[3];
    const float* bq   = (const float*)d_in[4];
    const float* wk   = (const float*)d_in[5];
    const float* bk   = (const float*)d_in[6];
    const float* wv   = (const float*)d_in[7];
    const float* bv   = (const float*)d_in[8];
    const float* wo   = (const float*)d_in[9];
    const float* bo   = (const float*)d_in[10];
    const float* ln1g = (const float*)d_in[11];
    const float* ln1b = (const float*)d_in[12];
    const float* w1   = (const float*)d_in[13];
    const float* b1   = (const float*)d_in[14];
    const float* w2   = (const float*)d_in[15];
    const float* b2   = (const float*)d_in[16];
    const float* ln2g = (const float*)d_in[17];
    const float* ln2b = (const float*)d_in[18];
    const float* wout = (const float*)d_in[19];
    const float* bout = (const float*)d_in[20];
    float* out = (float*)d_out;

    cudaFuncSetAttribute(gemm_h_kernel<true , true >, cudaFuncAttributeMaxDynamicSharedMemorySize, GEMM_SMEM);
    cudaFuncSetAttribute(gemm_h_kernel<false, true >, cudaFuncAttributeMaxDynamicSharedMemorySize, GEMM_SMEM);
    cudaFuncSetAttribute(gemm_h_kernel<true , false>, cudaFuncAttributeMaxDynamicSharedMemorySize, GEMM_SMEM);
    cudaFuncSetAttribute(gemm_h_kernel<false, false>, cudaFuncAttributeMaxDynamicSharedMemorySize, GEMM_SMEM);
    cudaFuncSetAttribute(attn_tc_kernel, cudaFuncAttributeMaxDynamicSharedMemorySize, ATT_SMEM);

    __half *WqkvT, *WoT, *W1T, *W2T, *WoutT, *h16, *qkv16, *att16, *ff16;
    float *bqkv, *h, *tmp;
    cudaGetSymbolAddress((void**)&WqkvT, g_WqkvT);
    cudaGetSymbolAddress((void**)&WoT,   g_WoT);
    cudaGetSymbolAddress((void**)&W1T,   g_W1T);
    cudaGetSymbolAddress((void**)&W2T,   g_W2T);
    cudaGetSymbolAddress((void**)&WoutT, g_WoutT);
    cudaGetSymbolAddress((void**)&bqkv,  g_bqkv);
    cudaGetSymbolAddress((void**)&h,     g_h);
    cudaGetSymbolAddress((void**)&h16,   g_h16);
    cudaGetSymbolAddress((void**)&qkv16, g_qkv16);
    cudaGetSymbolAddress((void**)&att16, g_att16);
    cudaGetSymbolAddress((void**)&ff16,  g_ff16);
    cudaGetSymbolAddress((void**)&tmp,   g_tmp);

    // weight conversion (once per replay)
    {
        int n = L_*QKVW*D_;
        pack_qkv_t_kernel<<<(n + 255)/256, 256>>>(wq, wk, wv, WqkvT);
        int nb = L_*QKVW;
        pack_bias_kernel<<<(nb + 255)/256, 256>>>(bq, bk, bv, bqkv);
        dim3 tb(32, 8);
        transpose_h_kernel<<<dim3(D_/32,  D_/32,  L_), tb>>>(wo,  WoT,  D_,  D_);
        transpose_h_kernel<<<dim3(FF_/32, D_/32,  L_), tb>>>(w1,  W1T,  D_,  FF_);
        transpose_h_kernel<<<dim3(D_/32,  FF_/32, L_), tb>>>(w2,  W2T,  FF_, D_);
        transpose_h_kernel<<<dim3(V_/32,  D_/32,  1 ), tb>>>(wout, WoutT, D_, V_);
    }

    // embedding (fp32 + fp16)
    embed_kernel<<<(ROWS*D_ + 255)/256, 256>>>(x, tok, pos, h, h16);

    for (int l = 0; l < L_; l++) {
        gemm_h(h16, WqkvT + (size_t)l*QKVW*D_, bqkv + (size_t)l*QKVW, qkv16,
               ROWS, QKVW, D_, false, true);

        dim3 ag(S_/128, B_*H_);
        attn_tc_kernel<<<ag, 128, ATT_SMEM>>>(qkv16, att16);

        gemm_h(att16, WoT + (size_t)l*D_*D_, bo + (size_t)l*D_, tmp,
               ROWS, D_, D_, false, false);
        add_ln_kernel<<<ROWS, 256>>>(tmp, h, h16, ln1g + (size_t)l*D_, ln1b + (size_t)l*D_);

        gemm_h(h16, W1T + (size_t)l*FF_*D_, b1 + (size_t)l*FF_, ff16,
               ROWS, FF_, D_, true, true);
        gemm_h(ff16, W2T + (size_t)l*D_*FF_, b2 + (size_t)l*D_, tmp,
               ROWS, D_, FF_, false, false);
        add_ln_kernel<<<ROWS, 256>>>(tmp, h, h16, ln2g + (size_t)l*D_, ln2b + (size_t)l*D_);
    }

    // final vocab projection + log_softmax (in-place on d_out)
    gemm_h(h16, WoutT, bout, out, ROWS, V_, D_, false, false);
    logsoftmax_kernel<<<ROWS, 256>>>(out);
}

// round 15
// speedup vs baseline: 2.1085x; 1.0467x over previous
#include <cuda_runtime.h>
#include <cuda_fp16.h>
#include <math.h>
#include <stdint.h>

// Model dims (fixed by the problem)
#define L_  8
#define H_  16
#define D_  1024
#define DH_ 64
#define FF_ 4096
#define V_  32000
#define S_  1024
#define B_  2
#define ROWS (B_*S_)   // 2048
#define QKVW (3*D_)    // 3072

// ---------------- scratch (static device globals; no allocation allowed) ----
__device__ __half g_WqkvT[L_*QKVW*D_];
__device__ __half g_WoT [L_*D_*D_];
__device__ __half g_W1T [L_*FF_*D_];
__device__ __half g_W2T [L_*D_*FF_];
__device__ __half g_WoutT[V_*D_];
__device__ float  g_bqkv[L_*QKVW];
// activations
__device__ float  g_h   [ROWS*D_];     // fp32 residual stream
__device__ __half g_h16 [ROWS*D_];
__device__ __half g_qkv16[ROWS*QKVW];
__device__ __half g_att16[ROWS*D_];
__device__ __half g_ff16 [ROWS*FF_];
__device__ float  g_tmp [ROWS*D_];

static __device__ __forceinline__ uint32_t h2_u32(__half2 v) {
    return *reinterpret_cast<uint32_t*>(&v);
}

// ---------------- weight conversion kernels ---------------------------------
// wq/wk/wv [L,H,D,DH]: per (l,h) transpose [D k][DH e] -> dst[L][3072 n][1024 k]
__global__ void transpose_qkv_kernel(const float* __restrict__ src, __half* __restrict__ dst,
                                     int sect) {
    __shared__ float t[32][33];
    const int z  = blockIdx.z;           // l*H + hd
    const int l  = z >> 4, hd = z & 15;
    const float* s = src + (size_t)z * D_ * DH_;          // [1024 k][64 e]
    __half* d = dst + (size_t)l*QKVW*D_ + (size_t)(sect*D_ + hd*DH_)*D_;
    const int p0 = blockIdx.y * 32, q0 = blockIdx.x * 32; // p over k, q over e
    const int tx = threadIdx.x, ty = threadIdx.y;
#pragma unroll
    for (int j = ty; j < 32; j += 8)
        t[j][tx] = s[(size_t)(p0+j)*DH_ + q0 + tx];
    __syncthreads();
#pragma unroll
    for (int j = ty; j < 32; j += 8)
        d[(size_t)(q0+j)*D_ + p0 + tx] = __float2half_rn(t[tx][j]);
}

__global__ void pack_bias_kernel(const float* __restrict__ bq, const float* __restrict__ bk,
                                 const float* __restrict__ bv, float* __restrict__ bias) {
    int i = blockIdx.x * blockDim.x + threadIdx.x;
    if (i >= L_*QKVW) return;
    int l = i / QKVW;
    int n = i - l*QKVW;
    int sect = n >> 10;
    int hn   = n & 1023;
    const float* src = (sect == 0) ? bq : (sect == 1 ? bk : bv);
    bias[i] = src[(size_t)l*D_ + hn];
}

// batched tiled transpose fp32 [z][P][Q] -> fp16 [z][Q][P]
__global__ void transpose_h_kernel(const float* __restrict__ src, __half* __restrict__ dst,
                                   int P, int Q) {
    __shared__ float t[32][33];
    const size_t off = (size_t)blockIdx.z * P * Q;
    const int p0 = blockIdx.y * 32, q0 = blockIdx.x * 32;
    const int tx = threadIdx.x, ty = threadIdx.y;
#pragma unroll
    for (int j = ty; j < 32; j += 8)
        t[j][tx] = src[off + (size_t)(p0+j)*Q + q0 + tx];
    __syncthreads();
#pragma unroll
    for (int j = ty; j < 32; j += 8)
        dst[off + (size_t)(q0+j)*P + p0 + tx] = __float2half_rn(t[tx][j]);
}

// ---------------- embedding: h = tok_emb[x] + pos_emb (fp32 + fp16) ---------
__global__ void embed_kernel(const int* __restrict__ x, const float* __restrict__ tok,
                             const float* __restrict__ pos, float* __restrict__ out,
                             __half* __restrict__ out16) {
    int i = blockIdx.x * blockDim.x + threadIdx.x;
    if (i >= ROWS*D_) return;
    int bs = i / D_;
    int d  = i - bs*D_;
    int s  = bs & (S_-1);
    int t  = x[bs];
    float v = tok[(size_t)t*D_ + d] + pos[(size_t)s*D_ + d];
    out[i] = v;
    out16[i] = __float2half_rn(v);
}

#define CP16(dst_u32, src_ptr) \
    asm volatile("cp.async.cg.shared.global [%0], [%1], 16;\n" :: "r"(dst_u32), "l"(src_ptr))

__device__ __forceinline__ void mma_f16(float c[4], const uint32_t a[4], const uint32_t b[2]) {
    asm volatile(
        "mma.sync.aligned.m16n8k16.row.col.f32.f16.f16.f32 "
        "{%0,%1,%2,%3}, {%4,%5,%6,%7}, {%8,%9}, {%0,%1,%2,%3};\n"
        : "+f"(c[0]), "+f"(c[1]), "+f"(c[2]), "+f"(c[3])
        : "r"(a[0]), "r"(a[1]), "r"(a[2]), "r"(a[3]), "r"(b[0]), "r"(b[1]));
}

// ---------------- fp16 tensor-core GEMM:  C = A[MxK] @ Wt[N][K]^T + bias ----
#define BM 128
#define BN 128
#define BK 32
#define WST 20
#define T_STAGE (BM*WST)
#define GEMM_SMEM (2*2*T_STAGE*4)           // 40960 bytes

template<bool RELU, bool OUT16>
__global__ __launch_bounds__(128, 3)
void gemm_h_kernel(const __half* __restrict__ A, const __half* __restrict__ Bt,
                   const float* __restrict__ bias, void* __restrict__ Cv,
                   int M, int N, int K) {
    extern __shared__ uint32_t smw[];
    uint32_t* AsW = smw;
    uint32_t* BsW = smw + 2*T_STAGE;

    const int tid   = threadIdx.x;
    const int warp  = tid >> 5;
    const int lane  = tid & 31;
    const int warpM = warp >> 1;
    const int warpN = warp & 1;
    const int gid   = lane >> 2;
    const int tig   = lane & 3;

    const int bm = blockIdx.y * BM;
    const int bn = blockIdx.x * BN;

    float acc[4][8][4];
#pragma unroll
    for (int mt = 0; mt < 4; mt++)
#pragma unroll
        for (int nt = 0; nt < 8; nt++)
#pragma unroll
            for (int i = 0; i < 4; i++) acc[mt][nt][i] = 0.f;

    const int KT = K / BK;

    auto copy_tile = [&](int k0, int st) {
        uint32_t* As = AsW + st*T_STAGE;
        uint32_t* Bs = BsW + st*T_STAGE;
#pragma unroll
        for (int i = 0; i < 4; i++) {
            int idx = tid + i*128;
            int row = idx >> 2;
            int ch  = idx & 3;
            const __half* src = A + (size_t)(bm + row)*K + k0 + ch*8;
            uint32_t dst = (uint32_t)__cvta_generic_to_shared(As + row*WST + ch*4);
            CP16(dst, src);
        }
#pragma unroll
        for (int i = 0; i < 4; i++) {
            int idx = tid + i*128;
            int row = idx >> 2;
            int ch  = idx & 3;
            const __half* src = Bt + (size_t)(bn + row)*K + k0 + ch*8;
            uint32_t dst = (uint32_t)__cvta_generic_to_shared(Bs + row*WST + ch*4);
            CP16(dst, src);
        }
        asm volatile("cp.async.commit_group;\n");
    };

    copy_tile(0, 0);

    for (int s = 0; s < KT; s++) {
        const int st = s & 1;
        asm volatile("cp.async.wait_group 0;\n");
        __syncthreads();
        if (s + 1 < KT) copy_tile((s + 1) * BK, st ^ 1);

        const uint32_t* As = AsW + st*T_STAGE;
        const uint32_t* Bs = BsW + st*T_STAGE;
#pragma unroll
        for (int kk = 0; kk < 2; kk++) {
            const int kw = kk * 8;
            uint32_t af[4][4];
#pragma unroll
            for (int mt = 0; mt < 4; mt++) {
                int r0 = warpM*64 + mt*16 + gid;
                af[mt][0] = As[(r0    )*WST + kw + tig    ];
                af[mt][1] = As[(r0 + 8)*WST + kw + tig    ];
                af[mt][2] = As[(r0    )*WST + kw + tig + 4];
                af[mt][3] = As[(r0 + 8)*WST + kw + tig + 4];
            }
#pragma unroll
            for (int nt = 0; nt < 8; nt++) {
                int c0 = warpN*64 + nt*8 + gid;
                uint32_t bf[2];
                bf[0] = Bs[c0*WST + kw + tig    ];
                bf[1] = Bs[c0*WST + kw + tig + 4];
#pragma unroll
                for (int mt = 0; mt < 4; mt++) mma_f16(acc[mt][nt], af[mt], bf);
            }
        }
        __syncthreads();
    }

#pragma unroll
    for (int mt = 0; mt < 4; mt++) {
#pragma unroll
        for (int nt = 0; nt < 8; nt++) {
            int row = bm + warpM*64 + mt*16 + gid;
            int col = bn + warpN*64 + nt*8 + tig*2;
            float b0 = bias[col], b1 = bias[col + 1];
            float v0 = acc[mt][nt][0] + b0;
            float v1 = acc[mt][nt][1] + b1;
            float v2 = acc[mt][nt][2] + b0;
            float v3 = acc[mt][nt][3] + b1;
            if (RELU) {
                v0 = fmaxf(v0, 0.f); v1 = fmaxf(v1, 0.f);
                v2 = fmaxf(v2, 0.f); v3 = fmaxf(v3, 0.f);
            }
            if (OUT16) {
                __half* C = (__half*)Cv;
                *(__half2*)(C + (size_t)row*N + col)       = __floats2half2_rn(v0, v1);
                *(__half2*)(C + (size_t)(row + 8)*N + col) = __floats2half2_rn(v2, v3);
            } else {
                float* C = (float*)Cv;
                *(float2*)(C + (size_t)row*N + col)       = make_float2(v0, v1);
                *(float2*)(C + (size_t)(row + 8)*N + col) = make_float2(v2, v3);
            }
        }
    }
}

// ---------------- fp16 tensor-core causal flash attention -------------------
// grid: (S/128, B*H), 128 threads (4 warps), warp = 32 query rows.
// Ks[key][dim] natural (QK^T B-frag pairs = consecutive dims);
// Vt[dim][key] transposed (PV B-frag pairs = consecutive keys);
// Ps fp16 [row][key]. Stride 72 halves (36 words) -> all frag LDS conflict-free.
#define ATSH 72
#define ATT_SMEM ((64*ATSH + 64*ATSH + 128*ATSH)*2)   // 36864 B

__global__ __launch_bounds__(128, 2)
void attn_tc_kernel(const __half* __restrict__ qkv, __half* __restrict__ o) {
    extern __shared__ __half hsm[];
    __half* Ks = hsm;                 // [64 keys][ATSH]
    __half* Vt = hsm + 64*ATSH;       // [64 dims][ATSH keys]
    __half* Ps = hsm + 128*ATSH;      // [128 rows][ATSH keys]

    const int tid  = threadIdx.x;
    const int warp = tid >> 5;
    const int lane = tid & 31;
    const int gid  = lane >> 2;
    const int tig  = lane & 3;
    const int q0   = blockIdx.x * 128;
    const int bh   = blockIdx.y;
    const int b    = bh >> 4;
    const int h    = bh & 15;
    const int wr0  = warp * 32;

    // ---- load Q fragments once (pre-scaled by 0.125, exact in fp16) ----
    const __half2 qsc = __floats2half2_rn(0.125f, 0.125f);
    uint32_t qa[2][4][4];
#pragma unroll
    for (int mt = 0; mt < 2; mt++) {
        int r1 = q0 + wr0 + mt*16 + gid;
        const __half* q1 = qkv + (size_t)(b*S_ + r1)*QKVW + h*DH_;
        const __half* q2 = q1 + (size_t)8*QKVW;
#pragma unroll
        for (int kc = 0; kc < 4; kc++) {
            __half2 t;
            t = __hmul2(*(const __half2*)(q1 + kc*16 + 2*tig    ), qsc); qa[mt][kc][0] = h2_u32(t);
            t = __hmul2(*(const __half2*)(q2 + kc*16 + 2*tig    ), qsc); qa[mt][kc][1] = h2_u32(t);
            t = __hmul2(*(const __half2*)(q1 + kc*16 + 2*tig + 8), qsc); qa[mt][kc][2] = h2_u32(t);
            t = __hmul2(*(const __half2*)(q2 + kc*16 + 2*tig + 8), qsc); qa[mt][kc][3] = h2_u32(t);
        }
    }

    float of[2][8][4];
#pragma unroll
    for (int mt = 0; mt < 2; mt++)
#pragma unroll
        for (int nt = 0; nt < 8; nt++)
#pragma unroll
            for (int i = 0; i < 4; i++) of[mt][nt][i] = 0.f;
    float m_r[2][2], l_r[2][2];
#pragma unroll
    for (int mt = 0; mt < 2; mt++) { m_r[mt][0] = m_r[mt][1] = -1e30f; l_r[mt][0] = l_r[mt][1] = 0.f; }

    const int ntiles = (q0 + 128) >> 6;

    for (int kt = 0; kt < ntiles; kt++) {
        const int kb0 = kt << 6;
        __syncthreads();

        // K tile: [64 keys][64 dims] natural, vectorized
#pragma unroll
        for (int i = 0; i < 4; i++) {
            int idx = tid + i*128;
            int key = idx >> 3;
            int c8  = (idx & 7) << 3;
            *(uint4*)(Ks + key*ATSH + c8) =
                *(const uint4*)(qkv + (size_t)(b*S_ + kb0 + key)*QKVW + D_ + h*DH_ + c8);
        }
        // V tile: transposed into Vt[dim][key]
#pragma unroll
        for (int i = 0; i < 4; i++) {
            int idx = tid + i*128;
            int key = idx >> 3;
            int c8  = (idx & 7) << 3;
            uint4 u = *(const uint4*)(qkv + (size_t)(b*S_ + kb0 + key)*QKVW + 2*D_ + h*DH_ + c8);
            const __half* hp = (const __half*)&u;
#pragma unroll
            for (int j = 0; j < 8; j++)
                Vt[(c8 + j)*ATSH + key] = hp[j];
        }
        __syncthreads();

        // ---- QK^T (fp16 m16n8k16) ----
        float sc[2][8][4];
#pragma unroll
        for (int mt = 0; mt < 2; mt++)
#pragma unroll
            for (int nt = 0; nt < 8; nt++)
#pragma unroll
                for (int i = 0; i < 4; i++) sc[mt][nt][i] = 0.f;
#pragma unroll
        for (int kc = 0; kc < 4; kc++) {
#pragma unroll
            for (int nt = 0; nt < 8; nt++) {
                uint32_t bf[2];
                bf[0] = *(const uint32_t*)(Ks + (nt*8 + gid)*ATSH + kc*16 + 2*tig    );
                bf[1] = *(const uint32_t*)(Ks + (nt*8 + gid)*ATSH + kc*16 + 2*tig + 8);
                mma_f16(sc[0][nt], qa[0][kc], bf);
                mma_f16(sc[1][nt], qa[1][kc], bf);
            }
        }

        // ---- causal mask + online softmax ----
#pragma unroll
        for (int mt = 0; mt < 2; mt++) {
            int r1 = q0 + wr0 + mt*16 + gid;
            int r2 = r1 + 8;
#pragma unroll
            for (int nt = 0; nt < 8; nt++) {
                int c0 = kb0 + nt*8 + tig*2;
                if (c0     > r1) sc[mt][nt][0] = -1e30f;
                if (c0 + 1 > r1) sc[mt][nt][1] = -1e30f;
                if (c0     > r2) sc[mt][nt][2] = -1e30f;
                if (c0 + 1 > r2) sc[mt][nt][3] = -1e30f;
            }
            float t1 = -1e30f, t2 = -1e30f;
#pragma unroll
            for (int nt = 0; nt < 8; nt++) {
                t1 = fmaxf(t1, fmaxf(sc[mt][nt][0], sc[mt][nt][1]));
                t2 = fmaxf(t2, fmaxf(sc[mt][nt][2], sc[mt][nt][3]));
            }
            t1 = fmaxf(t1, __shfl_xor_sync(0xffffffffu, t1, 1));
            t1 = fmaxf(t1, __shfl_xor_sync(0xffffffffu, t1, 2));
            t2 = fmaxf(t2, __shfl_xor_sync(0xffffffffu, t2, 1));
            t2 = fmaxf(t2, __shfl_xor_sync(0xffffffffu, t2, 2));
            float mn1 = fmaxf(m_r[mt][0], t1);
            float mn2 = fmaxf(m_r[mt][1], t2);
            float co1 = __expf(m_r[mt][0] - mn1);
            float co2 = __expf(m_r[mt][1] - mn2);
            float s1 = 0.f, s2 = 0.f;
            int lr = wr0 + mt*16 + gid;
#pragma unroll
            for (int nt = 0; nt < 8; nt++) {
                float p0 = __expf(sc[mt][nt][0] - mn1);
                float p1 = __expf(sc[mt][nt][1] - mn1);
                float p2 = __expf(sc[mt][nt][2] - mn2);
                float p3 = __expf(sc[mt][nt][3] - mn2);
                s1 += p0 + p1; s2 += p2 + p3;
                *(uint32_t*)(Ps + lr*ATSH + nt*8 + tig*2)       = h2_u32(__floats2half2_rn(p0, p1));
                *(uint32_t*)(Ps + (lr + 8)*ATSH + nt*8 + tig*2) = h2_u32(__floats2half2_rn(p2, p3));
            }
            s1 += __shfl_xor_sync(0xffffffffu, s1, 1);
            s1 += __shfl_xor_sync(0xffffffffu, s1, 2);
            s2 += __shfl_xor_sync(0xffffffffu, s2, 1);
            s2 += __shfl_xor_sync(0xffffffffu, s2, 2);
            l_r[mt][0] = l_r[mt][0]*co1 + s1;
            l_r[mt][1] = l_r[mt][1]*co2 + s2;
            m_r[mt][0] = mn1; m_r[mt][1] = mn2;
#pragma unroll
            for (int nt = 0; nt < 8; nt++) {
                of[mt][nt][0] *= co1; of[mt][nt][1] *= co1;
                of[mt][nt][2] *= co2; of[mt][nt][3] *= co2;
            }
        }
        __syncwarp();   // Ps rows are warp-private

        // ---- PV (fp16 m16n8k16) ----
#pragma unroll
        for (int kc = 0; kc < 4; kc++) {
            uint32_t pa[2][4];
#pragma unroll
            for (int mt = 0; mt < 2; mt++) {
                int lr = wr0 + mt*16 + gid;
                pa[mt][0] = *(const uint32_t*)(Ps + (lr    )*ATSH + kc*16 + 2*tig    );
                pa[mt][1] = *(const uint32_t*)(Ps + (lr + 8)*ATSH + kc*16 + 2*tig    );
                pa[mt][2] = *(const uint32_t*)(Ps + (lr    )*ATSH + kc*16 + 2*tig + 8);
                pa[mt][3] = *(const uint32_t*)(Ps + (lr + 8)*ATSH + kc*16 + 2*tig + 8);
            }
#pragma unroll
            for (int nt = 0; nt < 8; nt++) {
                uint32_t bf[2];
                bf[0] = *(const uint32_t*)(Vt + (nt*8 + gid)*ATSH + kc*16 + 2*tig    );
                bf[1] = *(const uint32_t*)(Vt + (nt*8 + gid)*ATSH + kc*16 + 2*tig + 8);
                mma_f16(of[0][nt], pa[0], bf);
                mma_f16(of[1][nt], pa[1], bf);
            }
        }
    }

    // ---- epilogue: normalize, store fp16 ----
#pragma unroll
    for (int mt = 0; mt < 2; mt++) {
        int r1 = q0 + wr0 + mt*16 + gid;
        float inv1 = 1.f / l_r[mt][0];
        float inv2 = 1.f / l_r[mt][1];
        __half* o1 = o + (size_t)(b*S_ + r1)*D_ + h*DH_;
        __half* o2 = o1 + (size_t)8*D_;
#pragma unroll
        for (int nt = 0; nt < 8; nt++) {
            int c = nt*8 + tig*2;
            *(__half2*)(o1 + c) = __floats2half2_rn(of[mt][nt][0]*inv1, of[mt][nt][1]*inv1);
            *(__half2*)(o2 + c) = __floats2half2_rn(of[mt][nt][2]*inv2, of[mt][nt][3]*inv2);
        }
    }
}

// ---------------- residual add + LayerNorm (fp32 + fp16 out) ----------------
__global__ void add_ln_kernel(const float* __restrict__ a, float* __restrict__ hres,
                              __half* __restrict__ h16,
                              const float* __restrict__ g, const float* __restrict__ bta) {
    const int row = blockIdx.x;
    const int tid = threadIdx.x;   // 256
    __shared__ float xs[D_];
    __shared__ float rbuf[2][8];
    __shared__ float stats[2];

    float s1 = 0.f, s2 = 0.f;
    for (int i = tid; i < D_; i += 256) {
        float x = a[(size_t)row*D_+i] + hres[(size_t)row*D_+i];
        xs[i] = x; s1 += x; s2 += x*x;
    }
#pragma unroll
    for (int off = 16; off; off >>= 1) {
        s1 += __shfl_down_sync(0xffffffffu, s1, off);
        s2 += __shfl_down_sync(0xffffffffu, s2, off);
    }
    if ((tid & 31) == 0) { rbuf[0][tid>>5] = s1; rbuf[1][tid>>5] = s2; }
    __syncthreads();
    if (tid == 0) {
        float t1 = 0.f, t2 = 0.f;
        for (int w = 0; w < 8; w++) { t1 += rbuf[0][w]; t2 += rbuf[1][w]; }
        float mu  = t1 * (1.f/D_);
        float var = t2 * (1.f/D_) - mu*mu;
        stats[0] = mu; stats[1] = rsqrtf(var + 1e-5f);
    }
    __syncthreads();
    float mu = stats[0], rstd = stats[1];
    for (int i = tid; i < D_; i += 256) {
        float v = (xs[i]-mu)*rstd*g[i] + bta[i];
        hres[(size_t)row*D_+i] = v;
        h16[(size_t)row*D_+i]  = __float2half_rn(v);
    }
}

// ---------------- log_softmax over V, in-place -------------------------------
__global__ void logsoftmax_kernel(float* __restrict__ out) {
    const int row = blockIdx.x;
    const int tid = threadIdx.x;   // 256
    float* p = out + (size_t)row * V_;
    __shared__ float rbuf[8];
    __shared__ float smax, slse;

    float lmax = -1e30f;
    for (int i = tid; i < V_; i += 256) lmax = fmaxf(lmax, p[i]);
#pragma unroll
    for (int off = 16; off; off >>= 1)
        lmax = fmaxf(lmax, __shfl_down_sync(0xffffffffu, lmax, off));
    if ((tid & 31) == 0) rbuf[tid>>5] = lmax;
    __syncthreads();
    if (tid == 0) {
        float mtot = -1e30f;
        for (int w = 0; w < 8; w++) mtot = fmaxf(mtot, rbuf[w]);
        smax = mtot;
    }
    __syncthreads();
    float mx = smax;

    float lsum = 0.f;
    for (int i = tid; i < V_; i += 256) lsum += __expf(p[i] - mx);
#pragma unroll
    for (int off = 16; off; off >>= 1)
        lsum += __shfl_down_sync(0xffffffffu, lsum, off);
    if ((tid & 31) == 0) rbuf[tid>>5] = lsum;
    __syncthreads();
    if (tid == 0) {
        float stot = 0.f;
        for (int w = 0; w < 8; w++) stot += rbuf[w];
        slse = logf(stot) + mx;
    }
    __syncthreads();
    float lse = slse;
    for (int i = tid; i < V_; i += 256) p[i] = p[i] - lse;
}

// ---------------- host-side helpers ------------------------------------------
static inline void gemm_h(const __half* A, const __half* Bt, const float* bias, void* C,
                          int M, int N, int K, bool relu, bool out16) {
    dim3 g(N/BN, M/BM);
    if (out16) {
        if (relu) gemm_h_kernel<true , true ><<<g, 128, GEMM_SMEM>>>(A, Bt, bias, C, M, N, K);
        else      gemm_h_kernel<false, true ><<<g, 128, GEMM_SMEM>>>(A, Bt, bias, C, M, N, K);
    } else {
        if (relu) gemm_h_kernel<true , false><<<g, 128, GEMM_SMEM>>>(A, Bt, bias, C, M, N, K);
        else      gemm_h_kernel<false, false><<<g, 128, GEMM_SMEM>>>(A, Bt, bias, C, M, N, K);
    }
}

extern "C" void kernel_launch(void* const* d_in, const int* in_sizes, int n_in,
                              void* d_out, int out_size) {
    const int*   x    = (const int*)  d_in[0];
    const float* tok  = (const float*)d_in[1];
    const float* pos  = (const float*)d_in[2];
    const float* wq   = (const float*)d_in[3];
    const float* bq   = (const float*)d_in[4];
    const float* wk   = (const float*)d_in[5];
    const float* bk   = (const float*)d_in[6];
    const float* wv   = (const float*)d_in[7];
    const float* bv   = (const float*)d_in[8];
    const float* wo   = (const float*)d_in[9];
    const float* bo   = (const float*)d_in[10];
    const float* ln1g = (const float*)d_in[11];
    const float* ln1b = (const float*)d_in[12];
    const float* w1   = (const float*)d_in[13];
    const float* b1   = (const float*)d_in[14];
    const float* w2   = (const float*)d_in[15];
    const float* b2   = (const float*)d_in[16];
    const float* ln2g = (const float*)d_in[17];
    const float* ln2b = (const float*)d_in[18];
    const float* wout = (const float*)d_in[19];
    const float* bout = (const float*)d_in[20];
    float* out = (float*)d_out;

    cudaFuncSetAttribute(gemm_h_kernel<true , true >, cudaFuncAttributeMaxDynamicSharedMemorySize, GEMM_SMEM);
    cudaFuncSetAttribute(gemm_h_kernel<false, true >, cudaFuncAttributeMaxDynamicSharedMemorySize, GEMM_SMEM);
    cudaFuncSetAttribute(gemm_h_kernel<true , false>, cudaFuncAttributeMaxDynamicSharedMemorySize, GEMM_SMEM);
    cudaFuncSetAttribute(gemm_h_kernel<false, false>, cudaFuncAttributeMaxDynamicSharedMemorySize, GEMM_SMEM);
    cudaFuncSetAttribute(attn_tc_kernel, cudaFuncAttributeMaxDynamicSharedMemorySize, ATT_SMEM);

    __half *WqkvT, *WoT, *W1T, *W2T, *WoutT, *h16, *qkv16, *att16, *ff16;
    float *bqkv, *h, *tmp;
    cudaGetSymbolAddress((void**)&WqkvT, g_WqkvT);
    cudaGetSymbolAddress((void**)&WoT,   g_WoT);
    cudaGetSymbolAddress((void**)&W1T,   g_W1T);
    cudaGetSymbolAddress((void**)&W2T,   g_W2T);
    cudaGetSymbolAddress((void**)&WoutT, g_WoutT);
    cudaGetSymbolAddress((void**)&bqkv,  g_bqkv);
    cudaGetSymbolAddress((void**)&h,     g_h);
    cudaGetSymbolAddress((void**)&h16,   g_h16);
    cudaGetSymbolAddress((void**)&qkv16, g_qkv16);
    cudaGetSymbolAddress((void**)&att16, g_att16);
    cudaGetSymbolAddress((void**)&ff16,  g_ff16);
    cudaGetSymbolAddress((void**)&tmp,   g_tmp);

    // weight conversion (coalesced tiled transposes)
    {
        dim3 tb(32, 8);
        transpose_qkv_kernel<<<dim3(DH_/32, D_/32, L_*H_), tb>>>(wq, WqkvT, 0);
        transpose_qkv_kernel<<<dim3(DH_/32, D_/32, L_*H_), tb>>>(wk, WqkvT, 1);
        transpose_qkv_kernel<<<dim3(DH_/32, D_/32, L_*H_), tb>>>(wv, WqkvT, 2);
        int nb = L_*QKVW;
        pack_bias_kernel<<<(nb + 255)/256, 256>>>(bq, bk, bv, bqkv);
        transpose_h_kernel<<<dim3(D_/32,  D_/32,  L_), tb>>>(wo,  WoT,  D_,  D_);
        transpose_h_kernel<<<dim3(FF_/32, D_/32,  L_), tb>>>(w1,  W1T,  D_,  FF_);
        transpose_h_kernel<<<dim3(D_/32,  FF_/32, L_), tb>>>(w2,  W2T,  FF_, D_);
        transpose_h_kernel<<<dim3(V_/32,  D_/32,  1 ), tb>>>(wout, WoutT, D_, V_);
    }

    // embedding (fp32 + fp16)
    embed_kernel<<<(ROWS*D_ + 255)/256, 256>>>(x, tok, pos, h, h16);

    for (int l = 0; l < L_; l++) {
        gemm_h(h16, WqkvT + (size_t)l*QKVW*D_, bqkv + (size_t)l*QKVW, qkv16,
               ROWS, QKVW, D_, false, true);

        dim3 ag(S_/128, B_*H_);
        attn_tc_kernel<<<ag, 128, ATT_SMEM>>>(qkv16, att16);

        gemm_h(att16, WoT + (size_t)l*D_*D_, bo + (size_t)l*D_, tmp,
               ROWS, D_, D_, false, false);
        add_ln_kernel<<<ROWS, 256>>>(tmp, h, h16, ln1g + (size_t)l*D_, ln1b + (size_t)l*D_);

        gemm_h(h16, W1T + (size_t)l*FF_*D_, b1 + (size_t)l*FF_, ff16,
               ROWS, FF_, D_, true, true);
        gemm_h(ff16, W2T + (size_t)l*D_*FF_, b2 + (size_t)l*D_, tmp,
               ROWS, D_, FF_, false, false);
        add_ln_kernel<<<ROWS, 256>>>(tmp, h, h16, ln2g + (size_t)l*D_, ln2b + (size_t)l*D_);
    }

    // final vocab projection + log_softmax (in-place on d_out)
    gemm_h(h16, WoutT, bout, out, ROWS, V_, D_, false, false);
    logsoftmax_kernel<<<ROWS, 256>>>(out);
}

// round 17
// speedup vs baseline: 2.1772x; 1.0326x over previous
#include <cuda_runtime.h>
#include <cuda_fp16.h>
#include <math.h>
#include <stdint.h>

// Model dims (fixed by the problem)
#define L_  8
#define H_  16
#define D_  1024
#define DH_ 64
#define FF_ 4096
#define V_  32000
#define S_  1024
#define B_  2
#define ROWS (B_*S_)   // 2048
#define QKVW (3*D_)    // 3072

// ---------------- scratch (static device globals; no allocation allowed) ----
__device__ __half g_WqkvT[L_*QKVW*D_];
__device__ __half g_WoT [L_*D_*D_];
__device__ __half g_W1T [L_*FF_*D_];
__device__ __half g_W2T [L_*D_*FF_];
__device__ __half g_WoutT[V_*D_];
__device__ float  g_bqkv[L_*QKVW];
// activations
__device__ float  g_h   [ROWS*D_];     // fp32 residual stream
__device__ __half g_h16 [ROWS*D_];
__device__ __half g_qkv16[ROWS*QKVW];
__device__ __half g_att16[ROWS*D_];
__device__ __half g_ff16 [ROWS*FF_];
__device__ float  g_tmp [ROWS*D_];

static __device__ __forceinline__ uint32_t h2_u32(__half2 v) {
    return *reinterpret_cast<uint32_t*>(&v);
}

// ---------------- weight conversion kernels ---------------------------------
__global__ void transpose_qkv_kernel(const float* __restrict__ src, __half* __restrict__ dst,
                                     int sect) {
    __shared__ float t[32][33];
    const int z  = blockIdx.z;           // l*H + hd
    const int l  = z >> 4, hd = z & 15;
    const float* s = src + (size_t)z * D_ * DH_;          // [1024 k][64 e]
    __half* d = dst + (size_t)l*QKVW*D_ + (size_t)(sect*D_ + hd*DH_)*D_;
    const int p0 = blockIdx.y * 32, q0 = blockIdx.x * 32;
    const int tx = threadIdx.x, ty = threadIdx.y;
#pragma unroll
    for (int j = ty; j < 32; j += 8)
        t[j][tx] = s[(size_t)(p0+j)*DH_ + q0 + tx];
    __syncthreads();
#pragma unroll
    for (int j = ty; j < 32; j += 8)
        d[(size_t)(q0+j)*D_ + p0 + tx] = __float2half_rn(t[tx][j]);
}

__global__ void pack_bias_kernel(const float* __restrict__ bq, const float* __restrict__ bk,
                                 const float* __restrict__ bv, float* __restrict__ bias) {
    int i = blockIdx.x * blockDim.x + threadIdx.x;
    if (i >= L_*QKVW) return;
    int l = i / QKVW;
    int n = i - l*QKVW;
    int sect = n >> 10;
    int hn   = n & 1023;
    const float* src = (sect == 0) ? bq : (sect == 1 ? bk : bv);
    bias[i] = src[(size_t)l*D_ + hn];
}

__global__ void transpose_h_kernel(const float* __restrict__ src, __half* __restrict__ dst,
                                   int P, int Q) {
    __shared__ float t[32][33];
    const size_t off = (size_t)blockIdx.z * P * Q;
    const int p0 = blockIdx.y * 32, q0 = blockIdx.x * 32;
    const int tx = threadIdx.x, ty = threadIdx.y;
#pragma unroll
    for (int j = ty; j < 32; j += 8)
        t[j][tx] = src[off + (size_t)(p0+j)*Q + q0 + tx];
    __syncthreads();
#pragma unroll
    for (int j = ty; j < 32; j += 8)
        dst[off + (size_t)(q0+j)*P + p0 + tx] = __float2half_rn(t[tx][j]);
}

// ---------------- embedding: h = tok_emb[x] + pos_emb (fp32 + fp16) ---------
__global__ void embed_kernel(const int* __restrict__ x, const float* __restrict__ tok,
                             const float* __restrict__ pos, float* __restrict__ out,
                             __half* __restrict__ out16) {
    int i = blockIdx.x * blockDim.x + threadIdx.x;
    if (i >= ROWS*D_) return;
    int bs = i / D_;
    int d  = i - bs*D_;
    int s  = bs & (S_-1);
    int t  = x[bs];
    float v = tok[(size_t)t*D_ + d] + pos[(size_t)s*D_ + d];
    out[i] = v;
    out16[i] = __float2half_rn(v);
}

#define CP16(dst_u32, src_ptr) \
    asm volatile("cp.async.cg.shared.global [%0], [%1], 16;\n" :: "r"(dst_u32), "l"(src_ptr))

#define LDSM_X4(r0, r1, r2, r3, addr) \
    asm volatile("ldmatrix.sync.aligned.m8n8.x4.shared.b16 {%0,%1,%2,%3}, [%4];" \
                 : "=r"(r0), "=r"(r1), "=r"(r2), "=r"(r3) : "r"(addr))

__device__ __forceinline__ void mma_f16(float c[4], const uint32_t a[4],
                                        uint32_t b0, uint32_t b1) {
    asm volatile(
        "mma.sync.aligned.m16n8k16.row.col.f32.f16.f16.f32 "
        "{%0,%1,%2,%3}, {%4,%5,%6,%7}, {%8,%9}, {%0,%1,%2,%3};\n"
        : "+f"(c[0]), "+f"(c[1]), "+f"(c[2]), "+f"(c[3])
        : "r"(a[0]), "r"(a[1]), "r"(a[2]), "r"(a[3]), "r"(b0), "r"(b1));
}

// ---------------- fp16 tensor-core GEMM:  C = A[MxK] @ Wt[N][K]^T + bias ----
// 128x128 CTA tile, BK=32, 128 threads (4 warps, 64x64), ldmatrix fragment
// loads, 2-stage cp.async, 3 CTAs/SM.
#define BM 128
#define BN 128
#define BK 32
#define WST 20                      // words/row (32 halves data + 8 halves pad)
#define T_STAGE (BM*WST)
#define GEMM_SMEM (2*2*T_STAGE*4)   // 40960 bytes

template<bool RELU, bool OUT16>
__global__ __launch_bounds__(128, 3)
void gemm_h_kernel(const __half* __restrict__ A, const __half* __restrict__ Bt,
                   const float* __restrict__ bias, void* __restrict__ Cv,
                   int M, int N, int K) {
    extern __shared__ uint32_t smw[];
    uint32_t* AsW = smw;
    uint32_t* BsW = smw + 2*T_STAGE;

    const int tid   = threadIdx.x;
    const int warp  = tid >> 5;
    const int lane  = tid & 31;
    const int warpM = warp >> 1;
    const int warpN = warp & 1;
    const int gid   = lane >> 2;
    const int tig   = lane & 3;

    const int bm = blockIdx.y * BM;
    const int bn = blockIdx.x * BN;

    // ldmatrix per-lane addressing (m8n8.x4: lane l -> matrix l>>3, row l&7)
    const int la  = lane & 7;
    const int lb3 = (lane >> 3) & 1;
    const int lb4 = (lane >> 4) & 1;
    const uint32_t baseA = (uint32_t)__cvta_generic_to_shared(AsW);
    const uint32_t baseB = (uint32_t)__cvta_generic_to_shared(BsW);
    // byte offsets: row*80 + halfoff*2
    const uint32_t aoff = (uint32_t)((warpM*64 + la + lb3*8) * 80 + (lb4*8) * 2);
    const uint32_t boff = (uint32_t)((warpN*64 + la + lb4*8) * 80 + (lb3*8) * 2);

    float acc[4][8][4];
#pragma unroll
    for (int mt = 0; mt < 4; mt++)
#pragma unroll
        for (int nt = 0; nt < 8; nt++)
#pragma unroll
            for (int i = 0; i < 4; i++) acc[mt][nt][i] = 0.f;

    const int KT = K / BK;

    auto copy_tile = [&](int k0, int st) {
        uint32_t* As = AsW + st*T_STAGE;
        uint32_t* Bs = BsW + st*T_STAGE;
#pragma unroll
        for (int i = 0; i < 4; i++) {
            int idx = tid + i*128;
            int row = idx >> 2;
            int ch  = idx & 3;
            const __half* src = A + (size_t)(bm + row)*K + k0 + ch*8;
            uint32_t dst = (uint32_t)__cvta_generic_to_shared(As + row*WST + ch*4);
            CP16(dst, src);
        }
#pragma unroll
        for (int i = 0; i < 4; i++) {
            int idx = tid + i*128;
            int row = idx >> 2;
            int ch  = idx & 3;
            const __half* src = Bt + (size_t)(bn + row)*K + k0 + ch*8;
            uint32_t dst = (uint32_t)__cvta_generic_to_shared(Bs + row*WST + ch*4);
            CP16(dst, src);
        }
        asm volatile("cp.async.commit_group;\n");
    };

    copy_tile(0, 0);

    for (int s = 0; s < KT; s++) {
        const int st = s & 1;
        asm volatile("cp.async.wait_group 0;\n");
        __syncthreads();
        if (s + 1 < KT) copy_tile((s + 1) * BK, st ^ 1);

        const uint32_t stA = baseA + (uint32_t)(st*T_STAGE*4) + aoff;
        const uint32_t stB = baseB + (uint32_t)(st*T_STAGE*4) + boff;
#pragma unroll
        for (int kk = 0; kk < 2; kk++) {
            const uint32_t kb = (uint32_t)(kk * 32);   // 16 halves = 32 bytes
            uint32_t af[4][4];
#pragma unroll
            for (int mt = 0; mt < 4; mt++)
                LDSM_X4(af[mt][0], af[mt][1], af[mt][2], af[mt][3],
                        stA + kb + (uint32_t)(mt*16*80));
            uint32_t bf[4][4];
#pragma unroll
            for (int p = 0; p < 4; p++)
                LDSM_X4(bf[p][0], bf[p][1], bf[p][2], bf[p][3],
                        stB + kb + (uint32_t)(p*16*80));
#pragma unroll
            for (int p = 0; p < 4; p++) {
#pragma unroll
                for (int mt = 0; mt < 4; mt++) {
                    mma_f16(acc[mt][2*p    ], af[mt], bf[p][0], bf[p][1]);
                    mma_f16(acc[mt][2*p + 1], af[mt], bf[p][2], bf[p][3]);
                }
            }
        }
        __syncthreads();
    }

#pragma unroll
    for (int mt = 0; mt < 4; mt++) {
#pragma unroll
        for (int nt = 0; nt < 8; nt++) {
            int row = bm + warpM*64 + mt*16 + gid;
            int col = bn + warpN*64 + nt*8 + tig*2;
            float b0 = bias[col], b1 = bias[col + 1];
            float v0 = acc[mt][nt][0] + b0;
            float v1 = acc[mt][nt][1] + b1;
            float v2 = acc[mt][nt][2] + b0;
            float v3 = acc[mt][nt][3] + b1;
            if (RELU) {
                v0 = fmaxf(v0, 0.f); v1 = fmaxf(v1, 0.f);
                v2 = fmaxf(v2, 0.f); v3 = fmaxf(v3, 0.f);
            }
            if (OUT16) {
                __half* C = (__half*)Cv;
                *(__half2*)(C + (size_t)row*N + col)       = __floats2half2_rn(v0, v1);
                *(__half2*)(C + (size_t)(row + 8)*N + col) = __floats2half2_rn(v2, v3);
            } else {
                float* C = (float*)Cv;
                *(float2*)(C + (size_t)row*N + col)       = make_float2(v0, v1);
                *(float2*)(C + (size_t)(row + 8)*N + col) = make_float2(v2, v3);
            }
        }
    }
}

// ---------------- fp16 tensor-core causal flash attention -------------------
#define ATSH 72
#define ATT_SMEM ((64*ATSH + 64*ATSH + 128*ATSH)*2)   // 36864 B

__global__ __launch_bounds__(128, 2)
void attn_tc_kernel(const __half* __restrict__ qkv, __half* __restrict__ o) {
    extern __shared__ __half hsm[];
    __half* Ks = hsm;                 // [64 keys][ATSH]
    __half* Vt = hsm + 64*ATSH;       // [64 dims][ATSH keys]
    __half* Ps = hsm + 128*ATSH;      // [128 rows][ATSH keys]

    const int tid  = threadIdx.x;
    const int warp = tid >> 5;
    const int lane = tid & 31;
    const int gid  = lane >> 2;
    const int tig  = lane & 3;
    const int q0   = blockIdx.x * 128;
    const int bh   = blockIdx.y;
    const int b    = bh >> 4;
    const int h    = bh & 15;
    const int wr0  = warp * 32;

    const __half2 qsc = __floats2half2_rn(0.125f, 0.125f);
    uint32_t qa[2][4][4];
#pragma unroll
    for (int mt = 0; mt < 2; mt++) {
        int r1 = q0 + wr0 + mt*16 + gid;
        const __half* q1 = qkv + (size_t)(b*S_ + r1)*QKVW + h*DH_;
        const __half* q2 = q1 + (size_t)8*QKVW;
#pragma unroll
        for (int kc = 0; kc < 4; kc++) {
            __half2 t;
            t = __hmul2(*(const __half2*)(q1 + kc*16 + 2*tig    ), qsc); qa[mt][kc][0] = h2_u32(t);
            t = __hmul2(*(const __half2*)(q2 + kc*16 + 2*tig    ), qsc); qa[mt][kc][1] = h2_u32(t);
            t = __hmul2(*(const __half2*)(q1 + kc*16 + 2*tig + 8), qsc); qa[mt][kc][2] = h2_u32(t);
            t = __hmul2(*(const __half2*)(q2 + kc*16 + 2*tig + 8), qsc); qa[mt][kc][3] = h2_u32(t);
        }
    }

    float of[2][8][4];
#pragma unroll
    for (int mt = 0; mt < 2; mt++)
#pragma unroll
        for (int nt = 0; nt < 8; nt++)
#pragma unroll
            for (int i = 0; i < 4; i++) of[mt][nt][i] = 0.f;
    float m_r[2][2], l_r[2][2];
#pragma unroll
    for (int mt = 0; mt < 2; mt++) { m_r[mt][0] = m_r[mt][1] = -1e30f; l_r[mt][0] = l_r[mt][1] = 0.f; }

    const int ntiles = (q0 + 128) >> 6;

    for (int kt = 0; kt < ntiles; kt++) {
        const int kb0 = kt << 6;
        __syncthreads();

#pragma unroll
        for (int i = 0; i < 4; i++) {
            int idx = tid + i*128;
            int key = idx >> 3;
            int c8  = (idx & 7) << 3;
            *(uint4*)(Ks + key*ATSH + c8) =
                *(const uint4*)(qkv + (size_t)(b*S_ + kb0 + key)*QKVW + D_ + h*DH_ + c8);
        }
#pragma unroll
        for (int i = 0; i < 4; i++) {
            int idx = tid + i*128;
            int key = idx >> 3;
            int c8  = (idx & 7) << 3;
            uint4 u = *(const uint4*)(qkv + (size_t)(b*S_ + kb0 + key)*QKVW + 2*D_ + h*DH_ + c8);
            const __half* hp = (const __half*)&u;
#pragma unroll
            for (int j = 0; j < 8; j++)
                Vt[(c8 + j)*ATSH + key] = hp[j];
        }
        __syncthreads();

        float sc[2][8][4];
#pragma unroll
        for (int mt = 0; mt < 2; mt++)
#pragma unroll
            for (int nt = 0; nt < 8; nt++)
#pragma unroll
                for (int i = 0; i < 4; i++) sc[mt][nt][i] = 0.f;
#pragma unroll
        for (int kc = 0; kc < 4; kc++) {
#pragma unroll
            for (int nt = 0; nt < 8; nt++) {
                uint32_t bf0 = *(const uint32_t*)(Ks + (nt*8 + gid)*ATSH + kc*16 + 2*tig    );
                uint32_t bf1 = *(const uint32_t*)(Ks + (nt*8 + gid)*ATSH + kc*16 + 2*tig + 8);
                mma_f16(sc[0][nt], qa[0][kc], bf0, bf1);
                mma_f16(sc[1][nt], qa[1][kc], bf0, bf1);
            }
        }

#pragma unroll
        for (int mt = 0; mt < 2; mt++) {
            int r1 = q0 + wr0 + mt*16 + gid;
            int r2 = r1 + 8;
#pragma unroll
            for (int nt = 0; nt < 8; nt++) {
                int c0 = kb0 + nt*8 + tig*2;
                if (c0     > r1) sc[mt][nt][0] = -1e30f;
                if (c0 + 1 > r1) sc[mt][nt][1] = -1e30f;
                if (c0     > r2) sc[mt][nt][2] = -1e30f;
                if (c0 + 1 > r2) sc[mt][nt][3] = -1e30f;
            }
            float t1 = -1e30f, t2 = -1e30f;
#pragma unroll
            for (int nt = 0; nt < 8; nt++) {
                t1 = fmaxf(t1, fmaxf(sc[mt][nt][0], sc[mt][nt][1]));
                t2 = fmaxf(t2, fmaxf(sc[mt][nt][2], sc[mt][nt][3]));
            }
            t1 = fmaxf(t1, __shfl_xor_sync(0xffffffffu, t1, 1));
            t1 = fmaxf(t1, __shfl_xor_sync(0xffffffffu, t1, 2));
            t2 = fmaxf(t2, __shfl_xor_sync(0xffffffffu, t2, 1));
            t2 = fmaxf(t2, __shfl_xor_sync(0xffffffffu, t2, 2));
            float mn1 = fmaxf(m_r[mt][0], t1);
            float mn2 = fmaxf(m_r[mt][1], t2);
            float co1 = __expf(m_r[mt][0] - mn1);
            float co2 = __expf(m_r[mt][1] - mn2);
            float s1 = 0.f, s2 = 0.f;
            int lr = wr0 + mt*16 + gid;
#pragma unroll
            for (int nt = 0; nt < 8; nt++) {
                float p0 = __expf(sc[mt][nt][0] - mn1);
                float p1 = __expf(sc[mt][nt][1] - mn1);
                float p2 = __expf(sc[mt][nt][2] - mn2);
                float p3 = __expf(sc[mt][nt][3] - mn2);
                s1 += p0 + p1; s2 += p2 + p3;
                *(uint32_t*)(Ps + lr*ATSH + nt*8 + tig*2)       = h2_u32(__floats2half2_rn(p0, p1));
                *(uint32_t*)(Ps + (lr + 8)*ATSH + nt*8 + tig*2) = h2_u32(__floats2half2_rn(p2, p3));
            }
            s1 += __shfl_xor_sync(0xffffffffu, s1, 1);
            s1 += __shfl_xor_sync(0xffffffffu, s1, 2);
            s2 += __shfl_xor_sync(0xffffffffu, s2, 1);
            s2 += __shfl_xor_sync(0xffffffffu, s2, 2);
            l_r[mt][0] = l_r[mt][0]*co1 + s1;
            l_r[mt][1] = l_r[mt][1]*co2 + s2;
            m_r[mt][0] = mn1; m_r[mt][1] = mn2;
#pragma unroll
            for (int nt = 0; nt < 8; nt++) {
                of[mt][nt][0] *= co1; of[mt][nt][1] *= co1;
                of[mt][nt][2] *= co2; of[mt][nt][3] *= co2;
            }
        }
        __syncwarp();

#pragma unroll
        for (int kc = 0; kc < 4; kc++) {
            uint32_t pa[2][4];
#pragma unroll
            for (int mt = 0; mt < 2; mt++) {
                int lr = wr0 + mt*16 + gid;
                pa[mt][0] = *(const uint32_t*)(Ps + (lr    )*ATSH + kc*16 + 2*tig    );
                pa[mt][1] = *(const uint32_t*)(Ps + (lr + 8)*ATSH + kc*16 + 2*tig    );
                pa[mt][2] = *(const uint32_t*)(Ps + (lr    )*ATSH + kc*16 + 2*tig + 8);
                pa[mt][3] = *(const uint32_t*)(Ps + (lr + 8)*ATSH + kc*16 + 2*tig + 8);
            }
#pragma unroll
            for (int nt = 0; nt < 8; nt++) {
                uint32_t bf0 = *(const uint32_t*)(Vt + (nt*8 + gid)*ATSH + kc*16 + 2*tig    );
                uint32_t bf1 = *(const uint32_t*)(Vt + (nt*8 + gid)*ATSH + kc*16 + 2*tig + 8);
                mma_f16(of[0][nt], pa[0], bf0, bf1);
                mma_f16(of[1][nt], pa[1], bf0, bf1);
            }
        }
    }

#pragma unroll
    for (int mt = 0; mt < 2; mt++) {
        int r1 = q0 + wr0 + mt*16 + gid;
        float inv1 = 1.f / l_r[mt][0];
        float inv2 = 1.f / l_r[mt][1];
        __half* o1 = o + (size_t)(b*S_ + r1)*D_ + h*DH_;
        __half* o2 = o1 + (size_t)8*D_;
#pragma unroll
        for (int nt = 0; nt < 8; nt++) {
            int c = nt*8 + tig*2;
            *(__half2*)(o1 + c) = __floats2half2_rn(of[mt][nt][0]*inv1, of[mt][nt][1]*inv1);
            *(__half2*)(o2 + c) = __floats2half2_rn(of[mt][nt][2]*inv2, of[mt][nt][3]*inv2);
        }
    }
}

// ---------------- residual add + LayerNorm (fp32 + fp16 out) ----------------
__global__ void add_ln_kernel(const float* __restrict__ a, float* __restrict__ hres,
                              __half* __restrict__ h16,
                              const float* __restrict__ g, const float* __restrict__ bta) {
    const int row = blockIdx.x;
    const int tid = threadIdx.x;   // 256
    __shared__ float xs[D_];
    __shared__ float rbuf[2][8];
    __shared__ float stats[2];

    float s1 = 0.f, s2 = 0.f;
    for (int i = tid; i < D_; i += 256) {
        float x = a[(size_t)row*D_+i] + hres[(size_t)row*D_+i];
        xs[i] = x; s1 += x; s2 += x*x;
    }
#pragma unroll
    for (int off = 16; off; off >>= 1) {
        s1 += __shfl_down_sync(0xffffffffu, s1, off);
        s2 += __shfl_down_sync(0xffffffffu, s2, off);
    }
    if ((tid & 31) == 0) { rbuf[0][tid>>5] = s1; rbuf[1][tid>>5] = s2; }
    __syncthreads();
    if (tid == 0) {
        float t1 = 0.f, t2 = 0.f;
        for (int w = 0; w < 8; w++) { t1 += rbuf[0][w]; t2 += rbuf[1][w]; }
        float mu  = t1 * (1.f/D_);
        float var = t2 * (1.f/D_) - mu*mu;
        stats[0] = mu; stats[1] = rsqrtf(var + 1e-5f);
    }
    __syncthreads();
    float mu = stats[0], rstd = stats[1];
    for (int i = tid; i < D_; i += 256) {
        float v = (xs[i]-mu)*rstd*g[i] + bta[i];
        hres[(size_t)row*D_+i] = v;
        h16[(size_t)row*D_+i]  = __float2half_rn(v);
    }
}

// ---------------- log_softmax over V, in-place -------------------------------
__global__ void logsoftmax_kernel(float* __restrict__ out) {
    const int row = blockIdx.x;
    const int tid = threadIdx.x;   // 256
    float* p = out + (size_t)row * V_;
    __shared__ float rbuf[8];
    __shared__ float smax, slse;

    float lmax = -1e30f;
    for (int i = tid; i < V_; i += 256) lmax = fmaxf(lmax, p[i]);
#pragma unroll
    for (int off = 16; off; off >>= 1)
        lmax = fmaxf(lmax, __shfl_down_sync(0xffffffffu, lmax, off));
    if ((tid & 31) == 0) rbuf[tid>>5] = lmax;
    __syncthreads();
    if (tid == 0) {
        float mtot = -1e30f;
        for (int w = 0; w < 8; w++) mtot = fmaxf(mtot, rbuf[w]);
        smax = mtot;
    }
    __syncthreads();
    float mx = smax;

    float lsum = 0.f;
    for (int i = tid; i < V_; i += 256) lsum += __expf(p[i] - mx);
#pragma unroll
    for (int off = 16; off; off >>= 1)
        lsum += __shfl_down_sync(0xffffffffu, lsum, off);
    if ((tid & 31) == 0) rbuf[tid>>5] = lsum;
    __syncthreads();
    if (tid == 0) {
        float stot = 0.f;
        for (int w = 0; w < 8; w++) stot += rbuf[w];
        slse = logf(stot) + mx;
    }
    __syncthreads();
    float lse = slse;
    for (int i = tid; i < V_; i += 256) p[i] = p[i] - lse;
}

// ---------------- host-side helpers ------------------------------------------
static inline void gemm_h(const __half* A, const __half* Bt, const float* bias, void* C,
                          int M, int N, int K, bool relu, bool out16) {
    dim3 g(N/BN, M/BM);
    if (out16) {
        if (relu) gemm_h_kernel<true , true ><<<g, 128, GEMM_SMEM>>>(A, Bt, bias, C, M, N, K);
        else      gemm_h_kernel<false, true ><<<g, 128, GEMM_SMEM>>>(A, Bt, bias, C, M, N, K);
    } else {
        if (relu) gemm_h_kernel<true , false><<<g, 128, GEMM_SMEM>>>(A, Bt, bias, C, M, N, K);
        else      gemm_h_kernel<false, false><<<g, 128, GEMM_SMEM>>>(A, Bt, bias, C, M, N, K);
    }
}

extern "C" void kernel_launch(void* const* d_in, const int* in_sizes, int n_in,
                              void* d_out, int out_size) {
    const int*   x    = (const int*)  d_in[0];
    const float* tok  = (const float*)d_in[1];
    const float* pos  = (const float*)d_in[2];
    const float* wq   = (const float*)d_in[3];
    const float* bq   = (const float*)d_in[4];
    const float* wk   = (const float*)d_in[5];
    const float* bk   = (const float*)d_in[6];
    const float* wv   = (const float*)d_in[7];
    const float* bv   = (const float*)d_in[8];
    const float* wo   = (const float*)d_in[9];
    const float* bo   = (const float*)d_in[10];
    const float* ln1g = (const float*)d_in[11];
    const float* ln1b = (const float*)d_in[12];
    const float* w1   = (const float*)d_in[13];
    const float* b1   = (const float*)d_in[14];
    const float* w2   = (const float*)d_in[15];
    const float* b2   = (const float*)d_in[16];
    const float* ln2g = (const float*)d_in[17];
    const float* ln2b = (const float*)d_in[18];
    const float* wout = (const float*)d_in[19];
    const float* bout = (const float*)d_in[20];
    float* out = (float*)d_out;

    cudaFuncSetAttribute(gemm_h_kernel<true , true >, cudaFuncAttributeMaxDynamicSharedMemorySize, GEMM_SMEM);
    cudaFuncSetAttribute(gemm_h_kernel<false, true >, cudaFuncAttributeMaxDynamicSharedMemorySize, GEMM_SMEM);
    cudaFuncSetAttribute(gemm_h_kernel<true , false>, cudaFuncAttributeMaxDynamicSharedMemorySize, GEMM_SMEM);
    cudaFuncSetAttribute(gemm_h_kernel<false, false>, cudaFuncAttributeMaxDynamicSharedMemorySize, GEMM_SMEM);
    cudaFuncSetAttribute(attn_tc_kernel, cudaFuncAttributeMaxDynamicSharedMemorySize, ATT_SMEM);

    __half *WqkvT, *WoT, *W1T, *W2T, *WoutT, *h16, *qkv16, *att16, *ff16;
    float *bqkv, *h, *tmp;
    cudaGetSymbolAddress((void**)&WqkvT, g_WqkvT);
    cudaGetSymbolAddress((void**)&WoT,   g_WoT);
    cudaGetSymbolAddress((void**)&W1T,   g_W1T);
    cudaGetSymbolAddress((void**)&W2T,   g_W2T);
    cudaGetSymbolAddress((void**)&WoutT, g_WoutT);
    cudaGetSymbolAddress((void**)&bqkv,  g_bqkv);
    cudaGetSymbolAddress((void**)&h,     g_h);
    cudaGetSymbolAddress((void**)&h16,   g_h16);
    cudaGetSymbolAddress((void**)&qkv16, g_qkv16);
    cudaGetSymbolAddress((void**)&att16, g_att16);
    cudaGetSymbolAddress((void**)&ff16,  g_ff16);
    cudaGetSymbolAddress((void**)&tmp,   g_tmp);

    // weight conversion (coalesced tiled transposes)
    {
        dim3 tb(32, 8);
        transpose_qkv_kernel<<<dim3(DH_/32, D_/32, L_*H_), tb>>>(wq, WqkvT, 0);
        transpose_qkv_kernel<<<dim3(DH_/32, D_/32, L_*H_), tb>>>(wk, WqkvT, 1);
        transpose_qkv_kernel<<<dim3(DH_/32, D_/32, L_*H_), tb>>>(wv, WqkvT, 2);
        int nb = L_*QKVW;
        pack_bias_kernel<<<(nb + 255)/256, 256>>>(bq, bk, bv, bqkv);
        transpose_h_kernel<<<dim3(D_/32,  D_/32,  L_), tb>>>(wo,  WoT,  D_,  D_);
        transpose_h_kernel<<<dim3(FF_/32, D_/32,  L_), tb>>>(w1,  W1T,  D_,  FF_);
        transpose_h_kernel<<<dim3(D_/32,  FF_/32, L_), tb>>>(w2,  W2T,  FF_, D_);
        transpose_h_kernel<<<dim3(V_/32,  D_/32,  1 ), tb>>>(wout, WoutT, D_, V_);
    }

    // embedding (fp32 + fp16)
    embed_kernel<<<(ROWS*D_ + 255)/256, 256>>>(x, tok, pos, h, h16);

    for (int l = 0; l < L_; l++) {
        gemm_h(h16, WqkvT + (size_t)l*QKVW*D_, bqkv + (size_t)l*QKVW, qkv16,
               ROWS, QKVW, D_, false, true);

        dim3 ag(S_/128, B_*H_);
        attn_tc_kernel<<<ag, 128, ATT_SMEM>>>(qkv16, att16);

        gemm_h(att16, WoT + (size_t)l*D_*D_, bo + (size_t)l*D_, tmp,
               ROWS, D_, D_, false, false);
        add_ln_kernel<<<ROWS, 256>>>(tmp, h, h16, ln1g + (size_t)l*D_, ln1b + (size_t)l*D_);

        gemm_h(h16, W1T + (size_t)l*FF_*D_, b1 + (size_t)l*FF_, ff16,
               ROWS, FF_, D_, true, true);
        gemm_h(ff16, W2T + (size_t)l*D_*FF_, b2 + (size_t)l*D_, tmp,
               ROWS, D_, FF_, false, false);
        add_ln_kernel<<<ROWS, 256>>>(tmp, h, h16, ln2g + (size_t)l*D_, ln2b + (size_t)l*D_);
    }

    // final vocab projection + log_softmax (in-place on d_out)
    gemm_h(h16, WoutT, bout, out, ROWS, V_, D_, false, false);
    logsoftmax_kernel<<<ROWS, 256>>>(out);
}